// round 13
// baseline (speedup 1.0000x reference)
#include <cuda_runtime.h>
#include <math.h>
#include <stdint.h>

#define NROWS 8192
#define CDIM  1024
#define HDIM  256
#define DFG   64
#define DCLS  128
#define NT    64
#define NPAIRS 2080
#define TAU_INV 5.0f
#define EPSF 1e-8f
#define NEGV (-1e9f)
#define PAD 132

typedef unsigned long long u64;

__device__ __forceinline__ u64 bcast2(float v) {
    u64 r; asm("mov.b64 %0, {%1, %1};" : "=l"(r) : "f"(v)); return r;
}
__device__ __forceinline__ void fma2(u64& d, u64 a, u64 b) {
    asm("fma.rn.f32x2 %0, %1, %2, %0;" : "+l"(d) : "l"(a), "l"(b));
}
__device__ __forceinline__ float2 unpack2(u64 v) {
    float2 r; asm("mov.b64 {%0, %1}, %2;" : "=f"(r.x), "=f"(r.y) : "l"(v)); return r;
}

__device__ float  g_h[NROWS * HDIM];
__device__ float  g_h2[NROWS * HDIM];
__device__ float  g_zfg[NROWS * DFG];
__device__ float  g_zcls[NROWS * DCLS];
__device__ float  g_T[NT * NROWS];
__device__ float  g_F[NT * NROWS];
__device__ float  g_E[NT * NROWS];
__device__ float  g_SP[NT * NROWS];
__device__ double g_bred[(NROWS / 8) * 4];
__device__ int    g_cnt[32];
__device__ int    g_lab[NROWS];

__global__ void prep_kernel(const int* __restrict__ w) {
    __shared__ int s;
    __shared__ int cnt[32];
    if (threadIdx.x == 0) s = 0;
    if (threadIdx.x < 32) cnt[threadIdx.x] = 0;
    __syncthreads();
    int local = 0;
    for (int i = threadIdx.x; i < NROWS / 2; i += 256)
        if (w[2 * i + 1] != 0) local = 1;
    if (local) atomicOr(&s, 1);
    __syncthreads();
    const int is32 = s;
    for (int i = threadIdx.x; i < NROWS; i += 256) {
        int l = is32 ? w[i] : w[2 * i];
        g_lab[i] = l;
        if (l >= 0 && l < 32) atomicAdd(&cnt[l], 1);
    }
    __syncthreads();
    if (threadIdx.x < 32) g_cnt[threadIdx.x] = cnt[threadIdx.x];
}

// 128x64 tile C = A@B + bias, relu. Double-buffered, FFMA2.
__device__ __forceinline__ void gemm_tile_relu(const float* __restrict__ A,
                                               const float* __restrict__ B,
                                               const float* __restrict__ bias,
                                               float* __restrict__ C,
                                               int N, int K, int row0, int col0) {
    __shared__ float As[2][16][132];
    __shared__ float Bs[2][16][68];
    const int tid = threadIdx.x;
    const int ty = tid >> 4, tx = tid & 15;
    const int mA = tid >> 2, kA = (tid & 3) << 2;
    const int kB = tid >> 4, nB = (tid & 15) << 2;
    u64 acc2[4][4];
#pragma unroll
    for (int i = 0; i < 4; ++i)
#pragma unroll
        for (int j = 0; j < 4; ++j) acc2[i][j] = 0ull;

    const float* pA0 = A + (size_t)(row0 + mA) * K + kA;
    const float* pA1 = A + (size_t)(row0 + mA + 64) * K + kA;
    const float* pB = B + (size_t)kB * N + col0 + nB;

    float4 ra0 = *(const float4*)pA0;
    float4 ra1 = *(const float4*)pA1;
    float4 rb = *(const float4*)pB;
    As[0][kA + 0][mA] = ra0.x; As[0][kA + 1][mA] = ra0.y;
    As[0][kA + 2][mA] = ra0.z; As[0][kA + 3][mA] = ra0.w;
    As[0][kA + 0][mA + 64] = ra1.x; As[0][kA + 1][mA + 64] = ra1.y;
    As[0][kA + 2][mA + 64] = ra1.z; As[0][kA + 3][mA + 64] = ra1.w;
    *(float4*)&Bs[0][kB][nB] = rb;
    __syncthreads();

    const int TI = K >> 4;
    for (int t = 0; t < TI; ++t) {
        const int cur = t & 1;
        if (t + 1 < TI) {
            const int k0 = (t + 1) << 4;
            ra0 = *(const float4*)(pA0 + k0);
            ra1 = *(const float4*)(pA1 + k0);
            rb = *(const float4*)(pB + (size_t)k0 * N);
        }
#pragma unroll
        for (int kk = 0; kk < 16; ++kk) {
            const float* ar = &As[cur][kk][ty * 8];
            ulonglong2 a01 = *(const ulonglong2*)ar;
            ulonglong2 a23 = *(const ulonglong2*)(ar + 4);
            u64 pa[4] = {a01.x, a01.y, a23.x, a23.y};
            float4 b = *(const float4*)&Bs[cur][kk][tx * 4];
            u64 pb[4] = {bcast2(b.x), bcast2(b.y), bcast2(b.z), bcast2(b.w)};
#pragma unroll
            for (int i = 0; i < 4; ++i)
#pragma unroll
                for (int j = 0; j < 4; ++j) fma2(acc2[i][j], pa[i], pb[j]);
        }
        if (t + 1 < TI) {
            const int nxt = cur ^ 1;
            As[nxt][kA + 0][mA] = ra0.x; As[nxt][kA + 1][mA] = ra0.y;
            As[nxt][kA + 2][mA] = ra0.z; As[nxt][kA + 3][mA] = ra0.w;
            As[nxt][kA + 0][mA + 64] = ra1.x; As[nxt][kA + 1][mA + 64] = ra1.y;
            As[nxt][kA + 2][mA + 64] = ra1.z; As[nxt][kA + 3][mA + 64] = ra1.w;
            *(float4*)&Bs[nxt][kB][nB] = rb;
        }
        __syncthreads();
    }
    float4 bb = *(const float4*)(bias + col0 + tx * 4);
    float bv[4] = {bb.x, bb.y, bb.z, bb.w};
#pragma unroll
    for (int i2 = 0; i2 < 4; ++i2) {
        float2 v0 = unpack2(acc2[i2][0]);
        float2 v1 = unpack2(acc2[i2][1]);
        float2 v2 = unpack2(acc2[i2][2]);
        float2 v3 = unpack2(acc2[i2][3]);
        float4 o0, o1;
        o0.x = fmaxf(v0.x + bv[0], 0.f); o0.y = fmaxf(v1.x + bv[1], 0.f);
        o0.z = fmaxf(v2.x + bv[2], 0.f); o0.w = fmaxf(v3.x + bv[3], 0.f);
        o1.x = fmaxf(v0.y + bv[0], 0.f); o1.y = fmaxf(v1.y + bv[1], 0.f);
        o1.z = fmaxf(v2.y + bv[2], 0.f); o1.w = fmaxf(v3.y + bv[3], 0.f);
        *(float4*)(C + (size_t)(row0 + ty * 8 + 2 * i2) * N + col0 + tx * 4) = o0;
        *(float4*)(C + (size_t)(row0 + ty * 8 + 2 * i2 + 1) * N + col0 + tx * 4) = o1;
    }
}

__global__ void __launch_bounds__(256, 3) gemm1_dual(const float* __restrict__ A,
                                                     const float* __restrict__ B0,
                                                     const float* __restrict__ b0,
                                                     const float* __restrict__ B1,
                                                     const float* __restrict__ b1) {
    const float* B = blockIdx.z ? B1 : B0;
    const float* bias = blockIdx.z ? b1 : b0;
    float* C = blockIdx.z ? g_h2 : g_h;
    gemm_tile_relu(A, B, bias, C, HDIM, CDIM, blockIdx.x * 128, blockIdx.y * 64);
}

// layer-2 + fused L2 norm. y=0: fg 128x64. y=1: cls 128x128.
__global__ void __launch_bounds__(256) gemm2_fused(const float* __restrict__ Bf,
                                                   const float* __restrict__ bf,
                                                   const float* __restrict__ Bc,
                                                   const float* __restrict__ bc) {
    __shared__ float As[2][16][132];
    __shared__ float Bs[2][16][132];
    const int tid = threadIdx.x;
    const int ty = tid >> 4, tx = tid & 15;
    const int mA = tid >> 2, kA = (tid & 3) << 2;
    const int row0 = blockIdx.x * 128;
    const int TI = HDIM >> 4;

    if (blockIdx.y == 0) {
        const int kB = tid >> 4, nB = (tid & 15) << 2;
        u64 acc2[4][4];
#pragma unroll
        for (int i = 0; i < 4; ++i)
#pragma unroll
            for (int j = 0; j < 4; ++j) acc2[i][j] = 0ull;
        const float* pA0 = g_h + (size_t)(row0 + mA) * HDIM + kA;
        const float* pA1 = g_h + (size_t)(row0 + mA + 64) * HDIM + kA;
        const float* pB = Bf + (size_t)kB * DFG + nB;
        float4 ra0 = *(const float4*)pA0;
        float4 ra1 = *(const float4*)pA1;
        float4 rb = *(const float4*)pB;
        As[0][kA + 0][mA] = ra0.x; As[0][kA + 1][mA] = ra0.y;
        As[0][kA + 2][mA] = ra0.z; As[0][kA + 3][mA] = ra0.w;
        As[0][kA + 0][mA + 64] = ra1.x; As[0][kA + 1][mA + 64] = ra1.y;
        As[0][kA + 2][mA + 64] = ra1.z; As[0][kA + 3][mA + 64] = ra1.w;
        *(float4*)&Bs[0][kB][nB] = rb;
        __syncthreads();
        for (int t = 0; t < TI; ++t) {
            const int cur = t & 1;
            if (t + 1 < TI) {
                const int k0 = (t + 1) << 4;
                ra0 = *(const float4*)(pA0 + k0);
                ra1 = *(const float4*)(pA1 + k0);
                rb = *(const float4*)(pB + (size_t)k0 * DFG);
            }
#pragma unroll
            for (int kk = 0; kk < 16; ++kk) {
                const float* ar = &As[cur][kk][ty * 8];
                ulonglong2 a01 = *(const ulonglong2*)ar;
                ulonglong2 a23 = *(const ulonglong2*)(ar + 4);
                u64 pa[4] = {a01.x, a01.y, a23.x, a23.y};
                float4 b = *(const float4*)&Bs[cur][kk][tx * 4];
                u64 pb[4] = {bcast2(b.x), bcast2(b.y), bcast2(b.z), bcast2(b.w)};
#pragma unroll
                for (int i = 0; i < 4; ++i)
#pragma unroll
                    for (int j = 0; j < 4; ++j) fma2(acc2[i][j], pa[i], pb[j]);
            }
            if (t + 1 < TI) {
                const int nxt = cur ^ 1;
                As[nxt][kA + 0][mA] = ra0.x; As[nxt][kA + 1][mA] = ra0.y;
                As[nxt][kA + 2][mA] = ra0.z; As[nxt][kA + 3][mA] = ra0.w;
                As[nxt][kA + 0][mA + 64] = ra1.x; As[nxt][kA + 1][mA + 64] = ra1.y;
                As[nxt][kA + 2][mA + 64] = ra1.z; As[nxt][kA + 3][mA + 64] = ra1.w;
                *(float4*)&Bs[nxt][kB][nB] = rb;
            }
            __syncthreads();
        }
        float4 bb = *(const float4*)(bf + tx * 4);
        float bv[4] = {bb.x, bb.y, bb.z, bb.w};
        float v[8][4];
#pragma unroll
        for (int i2 = 0; i2 < 4; ++i2)
#pragma unroll
            for (int j = 0; j < 4; ++j) {
                float2 p = unpack2(acc2[i2][j]);
                v[2 * i2][j] = p.x + bv[j];
                v[2 * i2 + 1][j] = p.y + bv[j];
            }
#pragma unroll
        for (int r = 0; r < 8; ++r) {
            float s = v[r][0] * v[r][0] + v[r][1] * v[r][1] +
                      v[r][2] * v[r][2] + v[r][3] * v[r][3];
#pragma unroll
            for (int off = 8; off > 0; off >>= 1) s += __shfl_xor_sync(0xffffffffu, s, off, 16);
            float inv = 1.f / fmaxf(sqrtf(s), EPSF);
            float4 o;
            o.x = v[r][0] * inv; o.y = v[r][1] * inv;
            o.z = v[r][2] * inv; o.w = v[r][3] * inv;
            *(float4*)(g_zfg + (size_t)(row0 + ty * 8 + r) * DFG + tx * 4) = o;
        }
    } else {
        const int kB = tid >> 4, nB = (tid & 15) << 3;
        u64 acc2[4][8];
#pragma unroll
        for (int i = 0; i < 4; ++i)
#pragma unroll
            for (int j = 0; j < 8; ++j) acc2[i][j] = 0ull;
        const float* pA0 = g_h2 + (size_t)(row0 + mA) * HDIM + kA;
        const float* pA1 = g_h2 + (size_t)(row0 + mA + 64) * HDIM + kA;
        const float* pB = Bc + (size_t)kB * DCLS + nB;
        float4 ra0 = *(const float4*)pA0;
        float4 ra1 = *(const float4*)pA1;
        float4 rb0 = *(const float4*)pB;
        float4 rb1 = *(const float4*)(pB + 4);
        As[0][kA + 0][mA] = ra0.x; As[0][kA + 1][mA] = ra0.y;
        As[0][kA + 2][mA] = ra0.z; As[0][kA + 3][mA] = ra0.w;
        As[0][kA + 0][mA + 64] = ra1.x; As[0][kA + 1][mA + 64] = ra1.y;
        As[0][kA + 2][mA + 64] = ra1.z; As[0][kA + 3][mA + 64] = ra1.w;
        *(float4*)&Bs[0][kB][nB] = rb0;
        *(float4*)&Bs[0][kB][nB + 4] = rb1;
        __syncthreads();
        for (int t = 0; t < TI; ++t) {
            const int cur = t & 1;
            if (t + 1 < TI) {
                const int k0 = (t + 1) << 4;
                ra0 = *(const float4*)(pA0 + k0);
                ra1 = *(const float4*)(pA1 + k0);
                rb0 = *(const float4*)(pB + (size_t)k0 * DCLS);
                rb1 = *(const float4*)(pB + (size_t)k0 * DCLS + 4);
            }
#pragma unroll
            for (int kk = 0; kk < 16; ++kk) {
                const float* ar = &As[cur][kk][ty * 8];
                ulonglong2 a01 = *(const ulonglong2*)ar;
                ulonglong2 a23 = *(const ulonglong2*)(ar + 4);
                u64 pa[4] = {a01.x, a01.y, a23.x, a23.y};
                float4 b0 = *(const float4*)&Bs[cur][kk][tx * 8];
                float4 b1 = *(const float4*)&Bs[cur][kk][tx * 8 + 4];
                u64 pb[8] = {bcast2(b0.x), bcast2(b0.y), bcast2(b0.z), bcast2(b0.w),
                             bcast2(b1.x), bcast2(b1.y), bcast2(b1.z), bcast2(b1.w)};
#pragma unroll
                for (int i = 0; i < 4; ++i)
#pragma unroll
                    for (int j = 0; j < 8; ++j) fma2(acc2[i][j], pa[i], pb[j]);
            }
            if (t + 1 < TI) {
                const int nxt = cur ^ 1;
                As[nxt][kA + 0][mA] = ra0.x; As[nxt][kA + 1][mA] = ra0.y;
                As[nxt][kA + 2][mA] = ra0.z; As[nxt][kA + 3][mA] = ra0.w;
                As[nxt][kA + 0][mA + 64] = ra1.x; As[nxt][kA + 1][mA + 64] = ra1.y;
                As[nxt][kA + 2][mA + 64] = ra1.z; As[nxt][kA + 3][mA + 64] = ra1.w;
                *(float4*)&Bs[nxt][kB][nB] = rb0;
                *(float4*)&Bs[nxt][kB][nB + 4] = rb1;
            }
            __syncthreads();
        }
        float4 bb0 = *(const float4*)(bc + tx * 8);
        float4 bb1 = *(const float4*)(bc + tx * 8 + 4);
        float bv[8] = {bb0.x, bb0.y, bb0.z, bb0.w, bb1.x, bb1.y, bb1.z, bb1.w};
        float v[8][8];
#pragma unroll
        for (int i2 = 0; i2 < 4; ++i2)
#pragma unroll
            for (int j = 0; j < 8; ++j) {
                float2 p = unpack2(acc2[i2][j]);
                v[2 * i2][j] = p.x + bv[j];
                v[2 * i2 + 1][j] = p.y + bv[j];
            }
#pragma unroll
        for (int r = 0; r < 8; ++r) {
            float s = 0.f;
#pragma unroll
            for (int j = 0; j < 8; ++j) s += v[r][j] * v[r][j];
#pragma unroll
            for (int off = 8; off > 0; off >>= 1) s += __shfl_xor_sync(0xffffffffu, s, off, 16);
            float inv = 1.f / fmaxf(sqrtf(s), EPSF);
            float4 o0, o1;
            o0.x = v[r][0] * inv; o0.y = v[r][1] * inv;
            o0.z = v[r][2] * inv; o0.w = v[r][3] * inv;
            o1.x = v[r][4] * inv; o1.y = v[r][5] * inv;
            o1.z = v[r][6] * inv; o1.w = v[r][7] * inv;
            *(float4*)(g_zcls + (size_t)(row0 + ty * 8 + r) * DCLS + tx * 8) = o0;
            *(float4*)(g_zcls + (size_t)(row0 + ty * 8 + r) * DCLS + tx * 8 + 4) = o1;
        }
    }
}

__device__ __forceinline__ void decode_pair(int t, int& I, int& J) {
    int i = (int)((129.0f - sqrtf(16641.0f - 8.0f * (float)t)) * 0.5f);
    if (i < 0) i = 0;
    if (i > NT - 1) i = NT - 1;
    while (i * (129 - i) / 2 > t) --i;
    while ((i + 1) * (128 - i) / 2 <= t) ++i;
    I = i;
    J = i + (t - i * (129 - i) / 2);
}

// 512-thread sim tiles: tx = tid&31 (4 cols each), ty = tid>>5 (8 rows each)
__device__ void simfg_body(int pidx, float* sm) {
    float* Zr = sm;
    float* Zc = sm + 64 * PAD;
    float* fgI = sm + 2 * 64 * PAD;
    float* fgJ = fgI + 128;
    float* colbuf = sm;
    float* colbuf2 = sm + 16 * 132;
    const int tid = threadIdx.x;
    const int tx = tid & 31, ty = tid >> 5;
    int I, J;
    decode_pair(pidx, I, J);
    const int row0 = I * 128, col0 = J * 128;
    const bool diag = (I == J);

    for (int v = tid; v < 2048; v += 512) {
        int r = v >> 4, d4 = (v & 15) << 2;
        float4 q = *(const float4*)(g_zfg + (size_t)(row0 + r) * DFG + d4);
        Zr[(d4 + 0) * PAD + r] = q.x; Zr[(d4 + 1) * PAD + r] = q.y;
        Zr[(d4 + 2) * PAD + r] = q.z; Zr[(d4 + 3) * PAD + r] = q.w;
        float4 p = *(const float4*)(g_zfg + (size_t)(col0 + r) * DFG + d4);
        Zc[(d4 + 0) * PAD + r] = p.x; Zc[(d4 + 1) * PAD + r] = p.y;
        Zc[(d4 + 2) * PAD + r] = p.z; Zc[(d4 + 3) * PAD + r] = p.w;
    }
    if (tid < 128) {
        fgI[tid] = (g_lab[row0 + tid] > 0) ? 1.f : 0.f;
        fgJ[tid] = (g_lab[col0 + tid] > 0) ? 1.f : 0.f;
    }
    __syncthreads();

    u64 acc2[4][4];
#pragma unroll
    for (int i = 0; i < 4; ++i)
#pragma unroll
        for (int j = 0; j < 4; ++j) acc2[i][j] = 0ull;

#pragma unroll 8
    for (int k = 0; k < DFG; ++k) {
        const float* ar = &Zr[k * PAD + ty * 8];
        ulonglong2 a01 = *(const ulonglong2*)ar;
        ulonglong2 a23 = *(const ulonglong2*)(ar + 4);
        u64 pa[4] = {a01.x, a01.y, a23.x, a23.y};
        float4 b = *(const float4*)&Zc[k * PAD + tx * 4];
        u64 pb[4] = {bcast2(b.x), bcast2(b.y), bcast2(b.z), bcast2(b.w)};
#pragma unroll
        for (int i = 0; i < 4; ++i)
#pragma unroll
            for (int j = 0; j < 4; ++j) fma2(acc2[i][j], pa[i], pb[j]);
    }

    float fgIr[8];
#pragma unroll
    for (int i = 0; i < 8; ++i) fgIr[i] = fgI[ty * 8 + i];
    float rT[8], rF[8], cT[4], cF[4];
#pragma unroll
    for (int i = 0; i < 8; ++i) { rT[i] = 0.f; rF[i] = 0.f; }
#pragma unroll
    for (int j = 0; j < 4; ++j) { cT[j] = 0.f; cF[j] = 0.f; }

#pragma unroll
    for (int j = 0; j < 4; ++j) {
        float fj = fgJ[tx * 4 + j];
#pragma unroll
        for (int i2 = 0; i2 < 4; ++i2) {
            float2 v = unpack2(acc2[i2][j]);
            float e0 = __expf(v.x * TAU_INV);
            float e1 = __expf(v.y * TAU_INV);
            rT[2 * i2] += e0;     rF[2 * i2] += e0 * fj;
            rT[2 * i2 + 1] += e1; rF[2 * i2 + 1] += e1 * fj;
            cT[j] += e0 + e1;
            cF[j] += e0 * fgIr[2 * i2] + e1 * fgIr[2 * i2 + 1];
        }
    }
#pragma unroll
    for (int i = 0; i < 8; ++i) {
        float vT = rT[i], vF = rF[i];
#pragma unroll
        for (int off = 16; off > 0; off >>= 1) {
            vT += __shfl_down_sync(0xffffffffu, vT, off);
            vF += __shfl_down_sync(0xffffffffu, vF, off);
        }
        if (tx == 0) {
            int row = row0 + ty * 8 + i;
            g_T[(size_t)J * NROWS + row] = vT;
            g_F[(size_t)J * NROWS + row] = vF;
        }
    }
    __syncthreads();  // Zr dead; colbuf aliases
#pragma unroll
    for (int j = 0; j < 4; ++j) {
        colbuf[ty * 132 + tx * 4 + j] = cT[j];
        colbuf2[ty * 132 + tx * 4 + j] = cF[j];
    }
    __syncthreads();
    if (!diag && tid < 128) {
        float sT = 0.f, sF = 0.f;
#pragma unroll
        for (int t = 0; t < 16; ++t) {
            sT += colbuf[t * 132 + tid];
            sF += colbuf2[t * 132 + tid];
        }
        g_T[(size_t)I * NROWS + col0 + tid] = sT;
        g_F[(size_t)I * NROWS + col0 + tid] = sF;
    }
}

__device__ void simcls_body(int pidx, float* sm) {
    float* Zr = sm;
    float* Zc = sm + 64 * PAD;
    int* labI = (int*)(sm + 2 * 64 * PAD);
    int* labJ = labI + 128;
    float* colbuf = sm;
    float* colbuf2 = sm + 16 * 132;
    const int tid = threadIdx.x;
    const int tx = tid & 31, ty = tid >> 5;
    int I, J;
    decode_pair(pidx, I, J);
    const int row0 = I * 128, col0 = J * 128;
    const bool diag = (I == J);

    if (tid < 128) {
        labI[tid] = g_lab[row0 + tid];
        labJ[tid] = g_lab[col0 + tid];
    }

    u64 acc2[4][4];
#pragma unroll
    for (int i = 0; i < 4; ++i)
#pragma unroll
        for (int j = 0; j < 4; ++j) acc2[i][j] = 0ull;

#pragma unroll
    for (int c = 0; c < 2; ++c) {
        __syncthreads();
        const int kb = c * 64;
        for (int v = tid; v < 2048; v += 512) {
            int r = v >> 4, d4 = (v & 15) << 2;
            float4 q = *(const float4*)(g_zcls + (size_t)(row0 + r) * DCLS + kb + d4);
            Zr[(d4 + 0) * PAD + r] = q.x; Zr[(d4 + 1) * PAD + r] = q.y;
            Zr[(d4 + 2) * PAD + r] = q.z; Zr[(d4 + 3) * PAD + r] = q.w;
            float4 p = *(const float4*)(g_zcls + (size_t)(col0 + r) * DCLS + kb + d4);
            Zc[(d4 + 0) * PAD + r] = p.x; Zc[(d4 + 1) * PAD + r] = p.y;
            Zc[(d4 + 2) * PAD + r] = p.z; Zc[(d4 + 3) * PAD + r] = p.w;
        }
        __syncthreads();
#pragma unroll 8
        for (int k = 0; k < 64; ++k) {
            const float* ar = &Zr[k * PAD + ty * 8];
            ulonglong2 a01 = *(const ulonglong2*)ar;
            ulonglong2 a23 = *(const ulonglong2*)(ar + 4);
            u64 pa[4] = {a01.x, a01.y, a23.x, a23.y};
            float4 b = *(const float4*)&Zc[k * PAD + tx * 4];
            u64 pb[4] = {bcast2(b.x), bcast2(b.y), bcast2(b.z), bcast2(b.w)};
#pragma unroll
            for (int i = 0; i < 4; ++i)
#pragma unroll
                for (int j = 0; j < 4; ++j) fma2(acc2[i][j], pa[i], pb[j]);
        }
    }

    int lrow[8];
#pragma unroll
    for (int i = 0; i < 8; ++i) lrow[i] = labI[ty * 8 + i];
    float rE[8], rS[8], cE[4], cS[4];
#pragma unroll
    for (int i = 0; i < 8; ++i) { rE[i] = 0.f; rS[i] = 0.f; }
#pragma unroll
    for (int j = 0; j < 4; ++j) { cE[j] = 0.f; cS[j] = 0.f; }

#pragma unroll
    for (int j = 0; j < 4; ++j) {
        int lc = labJ[tx * 4 + j];
#pragma unroll
        for (int i2 = 0; i2 < 4; ++i2) {
            float2 v = unpack2(acc2[i2][j]);
            float s0 = v.x * TAU_INV, s1 = v.y * TAU_INV;
            float e0 = __expf(s0), e1 = __expf(s1);
            rE[2 * i2] += e0;     rE[2 * i2 + 1] += e1;
            cE[j] += e0 + e1;
            if (lc > 0) {
                if (lc == lrow[2 * i2])     { rS[2 * i2] += s0;     cS[j] += s0; }
                if (lc == lrow[2 * i2 + 1]) { rS[2 * i2 + 1] += s1; cS[j] += s1; }
            }
        }
    }
#pragma unroll
    for (int i = 0; i < 8; ++i) {
        float vE = rE[i], vS = rS[i];
#pragma unroll
        for (int off = 16; off > 0; off >>= 1) {
            vE += __shfl_down_sync(0xffffffffu, vE, off);
            vS += __shfl_down_sync(0xffffffffu, vS, off);
        }
        if (tx == 0) {
            int row = row0 + ty * 8 + i;
            g_E[(size_t)J * NROWS + row] = vE;
            g_SP[(size_t)J * NROWS + row] = vS;
        }
    }
    __syncthreads();
#pragma unroll
    for (int j = 0; j < 4; ++j) {
        colbuf[ty * 132 + tx * 4 + j] = cE[j];
        colbuf2[ty * 132 + tx * 4 + j] = cS[j];
    }
    __syncthreads();
    if (!diag && tid < 128) {
        float sE = 0.f, sS = 0.f;
#pragma unroll
        for (int t = 0; t < 16; ++t) {
            sE += colbuf[t * 132 + tid];
            sS += colbuf2[t * 132 + tid];
        }
        g_E[(size_t)I * NROWS + col0 + tid] = sE;
        g_SP[(size_t)I * NROWS + col0 + tid] = sS;
    }
}

__global__ void __launch_bounds__(512, 2) sim_both() {
    extern __shared__ float sm[];
    if (blockIdx.x < NPAIRS) simfg_body(blockIdx.x, sm);
    else simcls_body(blockIdx.x - NPAIRS, sm);
}

__global__ void __launch_bounds__(256) rowfinal_kernel(const float* __restrict__ ious) {
    const int wid = threadIdx.x >> 5, lane = threadIdx.x & 31;
    const int row = blockIdx.x * 8 + wid;

    float T = 0.f, F = 0.f, E = 0.f, SP = 0.f;
#pragma unroll
    for (int s = lane; s < NT; s += 32) {
        T += g_T[(size_t)s * NROWS + row];
        F += g_F[(size_t)s * NROWS + row];
        E += g_E[(size_t)s * NROWS + row];
        SP += g_SP[(size_t)s * NROWS + row];
    }
#pragma unroll
    for (int off = 16; off > 0; off >>= 1) {
        T += __shfl_xor_sync(0xffffffffu, T, off);
        F += __shfl_xor_sync(0xffffffffu, F, off);
        E += __shfl_xor_sync(0xffffffffu, E, off);
        SP += __shfl_xor_sync(0xffffffffu, SP, off);
    }
    float sfg = 0.f;
    for (int d = lane; d < DFG; d += 32) {
        float v = g_zfg[(size_t)row * DFG + d];
        sfg += v * v;
    }
    float scl = 0.f;
    for (int d = lane; d < DCLS; d += 32) {
        float v = g_zcls[(size_t)row * DCLS + d];
        scl += v * v;
    }
#pragma unroll
    for (int off = 16; off > 0; off >>= 1) {
        sfg += __shfl_xor_sync(0xffffffffu, sfg, off);
        scl += __shfl_xor_sync(0xffffffffu, scl, off);
    }

    __shared__ double red[8][4];
    if (lane == 0) {
        int l = g_lab[row];
        bool fg = (l > 0);
        float iou = ious[row];
        float iouw = (iou > 0.5f) ? iou : 0.f;

        float eii = __expf(sfg * TAU_INV);
        float Tex = T - eii;
        float Fex = F - (fg ? eii : 0.f);
        int nfg = NROWS - g_cnt[0];
        int n_pos = nfg - (fg ? 1 : 0);
        bool valid = fg && (n_pos > 0);
        float lossi = -logf((Fex + EPSF) / (Tex + 2.0f * EPSF));
        float w = valid ? iouw : 0.f;

        float sii_c = scl * TAU_INV;
        float Eex = E - __expf(sii_c);
        float SPex = SP - ((l > 0) ? sii_c : 0.f);
        float npc = (l > 0) ? (float)g_cnt[l] : 0.f;
        float dg = (l > 0) ? 1.f : 0.f;
        float L = logf(Eex);
        float slp = dg * NEGV + SPex - (npc - dg) * L;
        bool validc = fg && (npc > 0.f) && isfinite(L);
        float Lzi = validc ? (-slp / (npc + EPSF)) : 0.f;
        float wcv = validc ? iouw : 0.f;

        red[wid][0] = (double)w * (double)lossi;
        red[wid][1] = (double)w;
        red[wid][2] = (double)wcv * (double)Lzi;
        red[wid][3] = (double)wcv;
    }
    __syncthreads();
    if (threadIdx.x == 0) {
        double s0 = 0, s1 = 0, s2 = 0, s3 = 0;
#pragma unroll
        for (int i = 0; i < 8; ++i) {
            s0 += red[i][0]; s1 += red[i][1];
            s2 += red[i][2]; s3 += red[i][3];
        }
        g_bred[blockIdx.x * 4 + 0] = s0;
        g_bred[blockIdx.x * 4 + 1] = s1;
        g_bred[blockIdx.x * 4 + 2] = s2;
        g_bred[blockIdx.x * 4 + 3] = s3;
    }
}

__global__ void final_kernel(float* __restrict__ out) {
    __shared__ double sh[256][4];
    double a[4] = {0, 0, 0, 0};
    for (int b = threadIdx.x; b < NROWS / 8; b += 256) {
#pragma unroll
        for (int c = 0; c < 4; ++c) a[c] += g_bred[b * 4 + c];
    }
#pragma unroll
    for (int c = 0; c < 4; ++c) sh[threadIdx.x][c] = a[c];
    __syncthreads();
    for (int s = 128; s > 0; s >>= 1) {
        if (threadIdx.x < s) {
#pragma unroll
            for (int c = 0; c < 4; ++c) sh[threadIdx.x][c] += sh[threadIdx.x + s][c];
        }
        __syncthreads();
    }
    if (threadIdx.x == 0) {
        out[0] = (float)(sh[0][0] / (sh[0][1] + (double)EPSF));
        out[1] = (float)(sh[0][2] / (sh[0][3] + (double)EPSF));
    }
}

extern "C" void kernel_launch(void* const* d_in, const int* in_sizes, int n_in,
                              void* d_out, int out_size) {
    const float* roi   = (const float*)d_in[0];
    const int*   labw  = (const int*)d_in[1];
    const float* ious  = (const float*)d_in[2];
    const float* fg_w1 = (const float*)d_in[3];
    const float* fg_b1 = (const float*)d_in[4];
    const float* fg_w2 = (const float*)d_in[5];
    const float* fg_b2 = (const float*)d_in[6];
    const float* cl_w1 = (const float*)d_in[7];
    const float* cl_b1 = (const float*)d_in[8];
    const float* cl_w2 = (const float*)d_in[9];
    const float* cl_b2 = (const float*)d_in[10];
    float* out = (float*)d_out;

    static bool init = false;
    if (!init) {
        cudaFuncSetAttribute(sim_both, cudaFuncAttributeMaxDynamicSharedMemorySize, 100000);
        init = true;
    }

    prep_kernel<<<1, 256>>>(labw);
    gemm1_dual<<<dim3(NROWS / 128, HDIM / 64, 2), 256>>>(roi, fg_w1, fg_b1, cl_w1, cl_b1);
    gemm2_fused<<<dim3(NROWS / 128, 2), 256>>>(fg_w2, fg_b2, cl_w2, cl_b2);

    size_t smem_sim = (2 * 64 * PAD + 2 * 128) * sizeof(float);
    sim_both<<<2 * NPAIRS, 512, smem_sim>>>();

    rowfinal_kernel<<<NROWS / 8, 256>>>(ious);
    final_kernel<<<1, 256>>>(out);
}

// round 14
// speedup vs baseline: 1.0872x; 1.0872x over previous
#include <cuda_runtime.h>
#include <math.h>
#include <stdint.h>

#define NROWS 8192
#define CDIM  1024
#define HDIM  256
#define DFG   64
#define DCLS  128
#define NT    64
#define NPAIRS 2080
#define TAU_INV 5.0f
#define EPSF 1e-8f
#define NEGV (-1e9f)
#define PAD 132

typedef unsigned long long u64;

__device__ __forceinline__ u64 bcast2(float v) {
    u64 r; asm("mov.b64 %0, {%1, %1};" : "=l"(r) : "f"(v)); return r;
}
__device__ __forceinline__ void fma2(u64& d, u64 a, u64 b) {
    asm("fma.rn.f32x2 %0, %1, %2, %0;" : "+l"(d) : "l"(a), "l"(b));
}
__device__ __forceinline__ float2 unpack2(u64 v) {
    float2 r; asm("mov.b64 {%0, %1}, %2;" : "=f"(r.x), "=f"(r.y) : "l"(v)); return r;
}

__device__ float  g_h[NROWS * HDIM];
__device__ float  g_h2[NROWS * HDIM];
__device__ float  g_zfg[NROWS * DFG];
__device__ float  g_zcls[NROWS * DCLS];
__device__ float  g_T[NT * NROWS];
__device__ float  g_F[NT * NROWS];
__device__ float  g_E[NT * NROWS];
__device__ float  g_SP[NT * NROWS];
__device__ double g_bred[(NROWS / 8) * 4];
__device__ int    g_cnt[32];
__device__ int    g_lab[NROWS];

__global__ void prep_kernel(const int* __restrict__ w) {
    __shared__ int s;
    __shared__ int cnt[32];
    if (threadIdx.x == 0) s = 0;
    if (threadIdx.x < 32) cnt[threadIdx.x] = 0;
    __syncthreads();
    int local = 0;
    for (int i = threadIdx.x; i < NROWS / 2; i += 256)
        if (w[2 * i + 1] != 0) local = 1;
    if (local) atomicOr(&s, 1);
    __syncthreads();
    const int is32 = s;
    for (int i = threadIdx.x; i < NROWS; i += 256) {
        int l = is32 ? w[i] : w[2 * i];
        g_lab[i] = l;
        if (l >= 0 && l < 32) atomicAdd(&cnt[l], 1);
    }
    __syncthreads();
    if (threadIdx.x < 32) g_cnt[threadIdx.x] = cnt[threadIdx.x];
}

// 128x64 tile C = A@B + bias, relu. Double-buffered, FFMA2.
__device__ __forceinline__ void gemm_tile_relu(const float* __restrict__ A,
                                               const float* __restrict__ B,
                                               const float* __restrict__ bias,
                                               float* __restrict__ C,
                                               int N, int K, int row0, int col0) {
    __shared__ float As[2][16][132];
    __shared__ float Bs[2][16][68];
    const int tid = threadIdx.x;
    const int ty = tid >> 4, tx = tid & 15;
    const int mA = tid >> 2, kA = (tid & 3) << 2;
    const int kB = tid >> 4, nB = (tid & 15) << 2;
    u64 acc2[4][4];
#pragma unroll
    for (int i = 0; i < 4; ++i)
#pragma unroll
        for (int j = 0; j < 4; ++j) acc2[i][j] = 0ull;

    const float* pA0 = A + (size_t)(row0 + mA) * K + kA;
    const float* pA1 = A + (size_t)(row0 + mA + 64) * K + kA;
    const float* pB = B + (size_t)kB * N + col0 + nB;

    float4 ra0 = *(const float4*)pA0;
    float4 ra1 = *(const float4*)pA1;
    float4 rb = *(const float4*)pB;
    As[0][kA + 0][mA] = ra0.x; As[0][kA + 1][mA] = ra0.y;
    As[0][kA + 2][mA] = ra0.z; As[0][kA + 3][mA] = ra0.w;
    As[0][kA + 0][mA + 64] = ra1.x; As[0][kA + 1][mA + 64] = ra1.y;
    As[0][kA + 2][mA + 64] = ra1.z; As[0][kA + 3][mA + 64] = ra1.w;
    *(float4*)&Bs[0][kB][nB] = rb;
    __syncthreads();

    const int TI = K >> 4;
    for (int t = 0; t < TI; ++t) {
        const int cur = t & 1;
        if (t + 1 < TI) {
            const int k0 = (t + 1) << 4;
            ra0 = *(const float4*)(pA0 + k0);
            ra1 = *(const float4*)(pA1 + k0);
            rb = *(const float4*)(pB + (size_t)k0 * N);
        }
#pragma unroll
        for (int kk = 0; kk < 16; ++kk) {
            const float* ar = &As[cur][kk][ty * 8];
            ulonglong2 a01 = *(const ulonglong2*)ar;
            ulonglong2 a23 = *(const ulonglong2*)(ar + 4);
            u64 pa[4] = {a01.x, a01.y, a23.x, a23.y};
            float4 b = *(const float4*)&Bs[cur][kk][tx * 4];
            u64 pb[4] = {bcast2(b.x), bcast2(b.y), bcast2(b.z), bcast2(b.w)};
#pragma unroll
            for (int i = 0; i < 4; ++i)
#pragma unroll
                for (int j = 0; j < 4; ++j) fma2(acc2[i][j], pa[i], pb[j]);
        }
        if (t + 1 < TI) {
            const int nxt = cur ^ 1;
            As[nxt][kA + 0][mA] = ra0.x; As[nxt][kA + 1][mA] = ra0.y;
            As[nxt][kA + 2][mA] = ra0.z; As[nxt][kA + 3][mA] = ra0.w;
            As[nxt][kA + 0][mA + 64] = ra1.x; As[nxt][kA + 1][mA + 64] = ra1.y;
            As[nxt][kA + 2][mA + 64] = ra1.z; As[nxt][kA + 3][mA + 64] = ra1.w;
            *(float4*)&Bs[nxt][kB][nB] = rb;
        }
        __syncthreads();
    }
    float4 bb = *(const float4*)(bias + col0 + tx * 4);
    float bv[4] = {bb.x, bb.y, bb.z, bb.w};
#pragma unroll
    for (int i2 = 0; i2 < 4; ++i2) {
        float2 v0 = unpack2(acc2[i2][0]);
        float2 v1 = unpack2(acc2[i2][1]);
        float2 v2 = unpack2(acc2[i2][2]);
        float2 v3 = unpack2(acc2[i2][3]);
        float4 o0, o1;
        o0.x = fmaxf(v0.x + bv[0], 0.f); o0.y = fmaxf(v1.x + bv[1], 0.f);
        o0.z = fmaxf(v2.x + bv[2], 0.f); o0.w = fmaxf(v3.x + bv[3], 0.f);
        o1.x = fmaxf(v0.y + bv[0], 0.f); o1.y = fmaxf(v1.y + bv[1], 0.f);
        o1.z = fmaxf(v2.y + bv[2], 0.f); o1.w = fmaxf(v3.y + bv[3], 0.f);
        *(float4*)(C + (size_t)(row0 + ty * 8 + 2 * i2) * N + col0 + tx * 4) = o0;
        *(float4*)(C + (size_t)(row0 + ty * 8 + 2 * i2 + 1) * N + col0 + tx * 4) = o1;
    }
}

__global__ void __launch_bounds__(256, 3) gemm1_dual(const float* __restrict__ A,
                                                     const float* __restrict__ B0,
                                                     const float* __restrict__ b0,
                                                     const float* __restrict__ B1,
                                                     const float* __restrict__ b1) {
    const float* B = blockIdx.z ? B1 : B0;
    const float* bias = blockIdx.z ? b1 : b0;
    float* C = blockIdx.z ? g_h2 : g_h;
    gemm_tile_relu(A, B, bias, C, HDIM, CDIM, blockIdx.x * 128, blockIdx.y * 64);
}

// layer-2 + fused L2 norm. y=0: fg 128x64. y=1: cls 128x128 (conflict-free b).
__global__ void __launch_bounds__(256) gemm2_fused(const float* __restrict__ Bf,
                                                   const float* __restrict__ bf,
                                                   const float* __restrict__ Bc,
                                                   const float* __restrict__ bc) {
    __shared__ float As[2][16][132];
    __shared__ float Bs[2][16][132];
    const int tid = threadIdx.x;
    const int ty = tid >> 4, tx = tid & 15;
    const int mA = tid >> 2, kA = (tid & 3) << 2;
    const int row0 = blockIdx.x * 128;
    const int TI = HDIM >> 4;

    if (blockIdx.y == 0) {
        const int kB = tid >> 4, nB = (tid & 15) << 2;
        u64 acc2[4][4];
#pragma unroll
        for (int i = 0; i < 4; ++i)
#pragma unroll
            for (int j = 0; j < 4; ++j) acc2[i][j] = 0ull;
        const float* pA0 = g_h + (size_t)(row0 + mA) * HDIM + kA;
        const float* pA1 = g_h + (size_t)(row0 + mA + 64) * HDIM + kA;
        const float* pB = Bf + (size_t)kB * DFG + nB;
        float4 ra0 = *(const float4*)pA0;
        float4 ra1 = *(const float4*)pA1;
        float4 rb = *(const float4*)pB;
        As[0][kA + 0][mA] = ra0.x; As[0][kA + 1][mA] = ra0.y;
        As[0][kA + 2][mA] = ra0.z; As[0][kA + 3][mA] = ra0.w;
        As[0][kA + 0][mA + 64] = ra1.x; As[0][kA + 1][mA + 64] = ra1.y;
        As[0][kA + 2][mA + 64] = ra1.z; As[0][kA + 3][mA + 64] = ra1.w;
        *(float4*)&Bs[0][kB][nB] = rb;
        __syncthreads();
        for (int t = 0; t < TI; ++t) {
            const int cur = t & 1;
            if (t + 1 < TI) {
                const int k0 = (t + 1) << 4;
                ra0 = *(const float4*)(pA0 + k0);
                ra1 = *(const float4*)(pA1 + k0);
                rb = *(const float4*)(pB + (size_t)k0 * DFG);
            }
#pragma unroll
            for (int kk = 0; kk < 16; ++kk) {
                const float* ar = &As[cur][kk][ty * 8];
                ulonglong2 a01 = *(const ulonglong2*)ar;
                ulonglong2 a23 = *(const ulonglong2*)(ar + 4);
                u64 pa[4] = {a01.x, a01.y, a23.x, a23.y};
                float4 b = *(const float4*)&Bs[cur][kk][tx * 4];
                u64 pb[4] = {bcast2(b.x), bcast2(b.y), bcast2(b.z), bcast2(b.w)};
#pragma unroll
                for (int i = 0; i < 4; ++i)
#pragma unroll
                    for (int j = 0; j < 4; ++j) fma2(acc2[i][j], pa[i], pb[j]);
            }
            if (t + 1 < TI) {
                const int nxt = cur ^ 1;
                As[nxt][kA + 0][mA] = ra0.x; As[nxt][kA + 1][mA] = ra0.y;
                As[nxt][kA + 2][mA] = ra0.z; As[nxt][kA + 3][mA] = ra0.w;
                As[nxt][kA + 0][mA + 64] = ra1.x; As[nxt][kA + 1][mA + 64] = ra1.y;
                As[nxt][kA + 2][mA + 64] = ra1.z; As[nxt][kA + 3][mA + 64] = ra1.w;
                *(float4*)&Bs[nxt][kB][nB] = rb;
            }
            __syncthreads();
        }
        float4 bb = *(const float4*)(bf + tx * 4);
        float bv[4] = {bb.x, bb.y, bb.z, bb.w};
        float v[8][4];
#pragma unroll
        for (int i2 = 0; i2 < 4; ++i2)
#pragma unroll
            for (int j = 0; j < 4; ++j) {
                float2 p = unpack2(acc2[i2][j]);
                v[2 * i2][j] = p.x + bv[j];
                v[2 * i2 + 1][j] = p.y + bv[j];
            }
#pragma unroll
        for (int r = 0; r < 8; ++r) {
            float s = v[r][0] * v[r][0] + v[r][1] * v[r][1] +
                      v[r][2] * v[r][2] + v[r][3] * v[r][3];
#pragma unroll
            for (int off = 8; off > 0; off >>= 1) s += __shfl_xor_sync(0xffffffffu, s, off, 16);
            float inv = 1.f / fmaxf(sqrtf(s), EPSF);
            float4 o;
            o.x = v[r][0] * inv; o.y = v[r][1] * inv;
            o.z = v[r][2] * inv; o.w = v[r][3] * inv;
            *(float4*)(g_zfg + (size_t)(row0 + ty * 8 + r) * DFG + tx * 4) = o;
        }
    } else {
        // cls: accumulator cols = {tx*4..tx*4+3} U {64+tx*4..64+tx*4+3}
        const int kB = tid >> 4, nB = (tid & 15) << 3;
        u64 acc2[4][8];
#pragma unroll
        for (int i = 0; i < 4; ++i)
#pragma unroll
            for (int j = 0; j < 8; ++j) acc2[i][j] = 0ull;
        const float* pA0 = g_h2 + (size_t)(row0 + mA) * HDIM + kA;
        const float* pA1 = g_h2 + (size_t)(row0 + mA + 64) * HDIM + kA;
        const float* pB = Bc + (size_t)kB * DCLS + nB;
        float4 ra0 = *(const float4*)pA0;
        float4 ra1 = *(const float4*)pA1;
        float4 rb0 = *(const float4*)pB;
        float4 rb1 = *(const float4*)(pB + 4);
        As[0][kA + 0][mA] = ra0.x; As[0][kA + 1][mA] = ra0.y;
        As[0][kA + 2][mA] = ra0.z; As[0][kA + 3][mA] = ra0.w;
        As[0][kA + 0][mA + 64] = ra1.x; As[0][kA + 1][mA + 64] = ra1.y;
        As[0][kA + 2][mA + 64] = ra1.z; As[0][kA + 3][mA + 64] = ra1.w;
        *(float4*)&Bs[0][kB][nB] = rb0;
        *(float4*)&Bs[0][kB][nB + 4] = rb1;
        __syncthreads();
        for (int t = 0; t < TI; ++t) {
            const int cur = t & 1;
            if (t + 1 < TI) {
                const int k0 = (t + 1) << 4;
                ra0 = *(const float4*)(pA0 + k0);
                ra1 = *(const float4*)(pA1 + k0);
                rb0 = *(const float4*)(pB + (size_t)k0 * DCLS);
                rb1 = *(const float4*)(pB + (size_t)k0 * DCLS + 4);
            }
#pragma unroll
            for (int kk = 0; kk < 16; ++kk) {
                const float* ar = &As[cur][kk][ty * 8];
                ulonglong2 a01 = *(const ulonglong2*)ar;
                ulonglong2 a23 = *(const ulonglong2*)(ar + 4);
                u64 pa[4] = {a01.x, a01.y, a23.x, a23.y};
                float4 b0 = *(const float4*)&Bs[cur][kk][tx * 4];
                float4 b1 = *(const float4*)&Bs[cur][kk][64 + tx * 4];
                u64 pb[8] = {bcast2(b0.x), bcast2(b0.y), bcast2(b0.z), bcast2(b0.w),
                             bcast2(b1.x), bcast2(b1.y), bcast2(b1.z), bcast2(b1.w)};
#pragma unroll
                for (int i = 0; i < 4; ++i)
#pragma unroll
                    for (int j = 0; j < 8; ++j) fma2(acc2[i][j], pa[i], pb[j]);
            }
            if (t + 1 < TI) {
                const int nxt = cur ^ 1;
                As[nxt][kA + 0][mA] = ra0.x; As[nxt][kA + 1][mA] = ra0.y;
                As[nxt][kA + 2][mA] = ra0.z; As[nxt][kA + 3][mA] = ra0.w;
                As[nxt][kA + 0][mA + 64] = ra1.x; As[nxt][kA + 1][mA + 64] = ra1.y;
                As[nxt][kA + 2][mA + 64] = ra1.z; As[nxt][kA + 3][mA + 64] = ra1.w;
                *(float4*)&Bs[nxt][kB][nB] = rb0;
                *(float4*)&Bs[nxt][kB][nB + 4] = rb1;
            }
            __syncthreads();
        }
        float4 bb0 = *(const float4*)(bc + tx * 4);
        float4 bb1 = *(const float4*)(bc + 64 + tx * 4);
        float bv[8] = {bb0.x, bb0.y, bb0.z, bb0.w, bb1.x, bb1.y, bb1.z, bb1.w};
        float v[8][8];
#pragma unroll
        for (int i2 = 0; i2 < 4; ++i2)
#pragma unroll
            for (int j = 0; j < 8; ++j) {
                float2 p = unpack2(acc2[i2][j]);
                v[2 * i2][j] = p.x + bv[j];
                v[2 * i2 + 1][j] = p.y + bv[j];
            }
#pragma unroll
        for (int r = 0; r < 8; ++r) {
            float s = 0.f;
#pragma unroll
            for (int j = 0; j < 8; ++j) s += v[r][j] * v[r][j];
#pragma unroll
            for (int off = 8; off > 0; off >>= 1) s += __shfl_xor_sync(0xffffffffu, s, off, 16);
            float inv = 1.f / fmaxf(sqrtf(s), EPSF);
            float4 o0, o1;
            o0.x = v[r][0] * inv; o0.y = v[r][1] * inv;
            o0.z = v[r][2] * inv; o0.w = v[r][3] * inv;
            o1.x = v[r][4] * inv; o1.y = v[r][5] * inv;
            o1.z = v[r][6] * inv; o1.w = v[r][7] * inv;
            *(float4*)(g_zcls + (size_t)(row0 + ty * 8 + r) * DCLS + tx * 4) = o0;
            *(float4*)(g_zcls + (size_t)(row0 + ty * 8 + r) * DCLS + 64 + tx * 4) = o1;
        }
    }
}

__device__ __forceinline__ void decode_pair(int t, int& I, int& J) {
    int i = (int)((129.0f - sqrtf(16641.0f - 8.0f * (float)t)) * 0.5f);
    if (i < 0) i = 0;
    if (i > NT - 1) i = NT - 1;
    while (i * (129 - i) / 2 > t) --i;
    while ((i + 1) * (128 - i) / 2 <= t) ++i;
    I = i;
    J = i + (t - i * (129 - i) / 2);
}

// column owned by (tx, j): {tx*4+j : j<4} U {64+tx*4+(j-4) : j>=4}
__device__ __forceinline__ int jcol(int tx, int j) {
    return (j < 4) ? (tx * 4 + j) : (60 + tx * 4 + j);
}

__device__ void simfg_body(int pidx, float* sm) {
    float* Zr = sm;
    float* Zc = sm + 64 * PAD;
    float* fgI = sm + 2 * 64 * PAD;
    float* fgJ = fgI + 128;
    float* colbuf = sm;
    float* colbuf2 = sm + 16 * 132;
    const int tid = threadIdx.x;
    const int ty = tid >> 4, tx = tid & 15;
    int I, J;
    decode_pair(pidx, I, J);
    const int row0 = I * 128, col0 = J * 128;
    const bool diag = (I == J);

    for (int v = tid; v < 2048; v += 256) {
        int r = v >> 4, d4 = (v & 15) << 2;
        float4 q = *(const float4*)(g_zfg + (size_t)(row0 + r) * DFG + d4);
        Zr[(d4 + 0) * PAD + r] = q.x; Zr[(d4 + 1) * PAD + r] = q.y;
        Zr[(d4 + 2) * PAD + r] = q.z; Zr[(d4 + 3) * PAD + r] = q.w;
        float4 p = *(const float4*)(g_zfg + (size_t)(col0 + r) * DFG + d4);
        Zc[(d4 + 0) * PAD + r] = p.x; Zc[(d4 + 1) * PAD + r] = p.y;
        Zc[(d4 + 2) * PAD + r] = p.z; Zc[(d4 + 3) * PAD + r] = p.w;
    }
    if (tid < 128) {
        fgI[tid] = (g_lab[row0 + tid] > 0) ? 1.f : 0.f;
        fgJ[tid] = (g_lab[col0 + tid] > 0) ? 1.f : 0.f;
    }
    __syncthreads();

    u64 acc2[4][8];
#pragma unroll
    for (int i = 0; i < 4; ++i)
#pragma unroll
        for (int j = 0; j < 8; ++j) acc2[i][j] = 0ull;

#pragma unroll 8
    for (int k = 0; k < DFG; ++k) {
        const float* ar = &Zr[k * PAD + ty * 8];
        ulonglong2 a01 = *(const ulonglong2*)ar;
        ulonglong2 a23 = *(const ulonglong2*)(ar + 4);
        u64 pa[4] = {a01.x, a01.y, a23.x, a23.y};
        float4 b0 = *(const float4*)&Zc[k * PAD + tx * 4];
        float4 b1 = *(const float4*)&Zc[k * PAD + 64 + tx * 4];
        u64 pb[8] = {bcast2(b0.x), bcast2(b0.y), bcast2(b0.z), bcast2(b0.w),
                     bcast2(b1.x), bcast2(b1.y), bcast2(b1.z), bcast2(b1.w)};
#pragma unroll
        for (int i = 0; i < 4; ++i)
#pragma unroll
            for (int j = 0; j < 8; ++j) fma2(acc2[i][j], pa[i], pb[j]);
    }

    float fgIr[8];
#pragma unroll
    for (int i = 0; i < 8; ++i) fgIr[i] = fgI[ty * 8 + i];
    float rT[8], rF[8], cT[8], cF[8];
#pragma unroll
    for (int i = 0; i < 8; ++i) { rT[i] = 0.f; rF[i] = 0.f; cT[i] = 0.f; cF[i] = 0.f; }

#pragma unroll
    for (int j = 0; j < 8; ++j) {
        float fj = fgJ[jcol(tx, j)];
#pragma unroll
        for (int i2 = 0; i2 < 4; ++i2) {
            float2 v = unpack2(acc2[i2][j]);
            float e0 = __expf(v.x * TAU_INV);
            float e1 = __expf(v.y * TAU_INV);
            rT[2 * i2] += e0;     rF[2 * i2] += e0 * fj;
            rT[2 * i2 + 1] += e1; rF[2 * i2 + 1] += e1 * fj;
            cT[j] += e0 + e1;
            cF[j] += e0 * fgIr[2 * i2] + e1 * fgIr[2 * i2 + 1];
        }
    }
#pragma unroll
    for (int i = 0; i < 8; ++i) {
        float vT = rT[i], vF = rF[i];
#pragma unroll
        for (int off = 8; off > 0; off >>= 1) {
            vT += __shfl_down_sync(0xffffffffu, vT, off, 16);
            vF += __shfl_down_sync(0xffffffffu, vF, off, 16);
        }
        if (tx == 0) {
            int row = row0 + ty * 8 + i;
            g_T[(size_t)J * NROWS + row] = vT;
            g_F[(size_t)J * NROWS + row] = vF;
        }
    }
    __syncthreads();
#pragma unroll
    for (int j = 0; j < 8; ++j) {
        int c = jcol(tx, j);
        colbuf[ty * 132 + c] = cT[j];
        colbuf2[ty * 132 + c] = cF[j];
    }
    __syncthreads();
    if (!diag && tid < 128) {
        float sT = 0.f, sF = 0.f;
#pragma unroll
        for (int t = 0; t < 16; ++t) {
            sT += colbuf[t * 132 + tid];
            sF += colbuf2[t * 132 + tid];
        }
        g_T[(size_t)I * NROWS + col0 + tid] = sT;
        g_F[(size_t)I * NROWS + col0 + tid] = sF;
    }
}

__device__ void simcls_body(int pidx, float* sm) {
    float* Zr = sm;
    float* Zc = sm + 64 * PAD;
    int* labI = (int*)(sm + 2 * 64 * PAD);
    int* labJ = labI + 128;
    float* colbuf = sm;
    float* colbuf2 = sm + 16 * 132;
    const int tid = threadIdx.x;
    const int ty = tid >> 4, tx = tid & 15;
    int I, J;
    decode_pair(pidx, I, J);
    const int row0 = I * 128, col0 = J * 128;
    const bool diag = (I == J);

    if (tid < 128) {
        labI[tid] = g_lab[row0 + tid];
        labJ[tid] = g_lab[col0 + tid];
    }

    u64 acc2[4][8];
#pragma unroll
    for (int i = 0; i < 4; ++i)
#pragma unroll
        for (int j = 0; j < 8; ++j) acc2[i][j] = 0ull;

#pragma unroll
    for (int c = 0; c < 2; ++c) {
        __syncthreads();
        const int kb = c * 64;
        for (int v = tid; v < 2048; v += 256) {
            int r = v >> 4, d4 = (v & 15) << 2;
            float4 q = *(const float4*)(g_zcls + (size_t)(row0 + r) * DCLS + kb + d4);
            Zr[(d4 + 0) * PAD + r] = q.x; Zr[(d4 + 1) * PAD + r] = q.y;
            Zr[(d4 + 2) * PAD + r] = q.z; Zr[(d4 + 3) * PAD + r] = q.w;
            float4 p = *(const float4*)(g_zcls + (size_t)(col0 + r) * DCLS + kb + d4);
            Zc[(d4 + 0) * PAD + r] = p.x; Zc[(d4 + 1) * PAD + r] = p.y;
            Zc[(d4 + 2) * PAD + r] = p.z; Zc[(d4 + 3) * PAD + r] = p.w;
        }
        __syncthreads();
#pragma unroll 8
        for (int k = 0; k < 64; ++k) {
            const float* ar = &Zr[k * PAD + ty * 8];
            ulonglong2 a01 = *(const ulonglong2*)ar;
            ulonglong2 a23 = *(const ulonglong2*)(ar + 4);
            u64 pa[4] = {a01.x, a01.y, a23.x, a23.y};
            float4 b0 = *(const float4*)&Zc[k * PAD + tx * 4];
            float4 b1 = *(const float4*)&Zc[k * PAD + 64 + tx * 4];
            u64 pb[8] = {bcast2(b0.x), bcast2(b0.y), bcast2(b0.z), bcast2(b0.w),
                         bcast2(b1.x), bcast2(b1.y), bcast2(b1.z), bcast2(b1.w)};
#pragma unroll
            for (int i = 0; i < 4; ++i)
#pragma unroll
                for (int j = 0; j < 8; ++j) fma2(acc2[i][j], pa[i], pb[j]);
        }
    }

    int lrow[8];
#pragma unroll
    for (int i = 0; i < 8; ++i) lrow[i] = labI[ty * 8 + i];
    float rE[8], rS[8], cE[8], cS[8];
#pragma unroll
    for (int i = 0; i < 8; ++i) { rE[i] = 0.f; rS[i] = 0.f; cE[i] = 0.f; cS[i] = 0.f; }

#pragma unroll
    for (int j = 0; j < 8; ++j) {
        int lc = labJ[jcol(tx, j)];
#pragma unroll
        for (int i2 = 0; i2 < 4; ++i2) {
            float2 v = unpack2(acc2[i2][j]);
            float s0 = v.x * TAU_INV, s1 = v.y * TAU_INV;
            float e0 = __expf(s0), e1 = __expf(s1);
            rE[2 * i2] += e0;     rE[2 * i2 + 1] += e1;
            cE[j] += e0 + e1;
            if (lc > 0) {
                if (lc == lrow[2 * i2])     { rS[2 * i2] += s0;     cS[j] += s0; }
                if (lc == lrow[2 * i2 + 1]) { rS[2 * i2 + 1] += s1; cS[j] += s1; }
            }
        }
    }
#pragma unroll
    for (int i = 0; i < 8; ++i) {
        float vE = rE[i], vS = rS[i];
#pragma unroll
        for (int off = 8; off > 0; off >>= 1) {
            vE += __shfl_down_sync(0xffffffffu, vE, off, 16);
            vS += __shfl_down_sync(0xffffffffu, vS, off, 16);
        }
        if (tx == 0) {
            int row = row0 + ty * 8 + i;
            g_E[(size_t)J * NROWS + row] = vE;
            g_SP[(size_t)J * NROWS + row] = vS;
        }
    }
    __syncthreads();
#pragma unroll
    for (int j = 0; j < 8; ++j) {
        int c = jcol(tx, j);
        colbuf[ty * 132 + c] = cE[j];
        colbuf2[ty * 132 + c] = cS[j];
    }
    __syncthreads();
    if (!diag && tid < 128) {
        float sE = 0.f, sS = 0.f;
#pragma unroll
        for (int t = 0; t < 16; ++t) {
            sE += colbuf[t * 132 + tid];
            sS += colbuf2[t * 132 + tid];
        }
        g_E[(size_t)I * NROWS + col0 + tid] = sE;
        g_SP[(size_t)I * NROWS + col0 + tid] = sS;
    }
}

// cls tiles first (longest-job-first packing), fg backfills the tail
__global__ void __launch_bounds__(256, 2) sim_both() {
    extern __shared__ float sm[];
    if (blockIdx.x < NPAIRS) simcls_body(blockIdx.x, sm);
    else simfg_body(blockIdx.x - NPAIRS, sm);
}

__global__ void __launch_bounds__(256) rowfinal_kernel(const float* __restrict__ ious) {
    const int wid = threadIdx.x >> 5, lane = threadIdx.x & 31;
    const int row = blockIdx.x * 8 + wid;

    float T = 0.f, F = 0.f, E = 0.f, SP = 0.f;
#pragma unroll
    for (int s = lane; s < NT; s += 32) {
        T += g_T[(size_t)s * NROWS + row];
        F += g_F[(size_t)s * NROWS + row];
        E += g_E[(size_t)s * NROWS + row];
        SP += g_SP[(size_t)s * NROWS + row];
    }
#pragma unroll
    for (int off = 16; off > 0; off >>= 1) {
        T += __shfl_xor_sync(0xffffffffu, T, off);
        F += __shfl_xor_sync(0xffffffffu, F, off);
        E += __shfl_xor_sync(0xffffffffu, E, off);
        SP += __shfl_xor_sync(0xffffffffu, SP, off);
    }
    float sfg = 0.f;
    for (int d = lane; d < DFG; d += 32) {
        float v = g_zfg[(size_t)row * DFG + d];
        sfg += v * v;
    }
    float scl = 0.f;
    for (int d = lane; d < DCLS; d += 32) {
        float v = g_zcls[(size_t)row * DCLS + d];
        scl += v * v;
    }
#pragma unroll
    for (int off = 16; off > 0; off >>= 1) {
        sfg += __shfl_xor_sync(0xffffffffu, sfg, off);
        scl += __shfl_xor_sync(0xffffffffu, scl, off);
    }

    __shared__ double red[8][4];
    if (lane == 0) {
        int l = g_lab[row];
        bool fg = (l > 0);
        float iou = ious[row];
        float iouw = (iou > 0.5f) ? iou : 0.f;

        float eii = __expf(sfg * TAU_INV);
        float Tex = T - eii;
        float Fex = F - (fg ? eii : 0.f);
        int nfg = NROWS - g_cnt[0];
        int n_pos = nfg - (fg ? 1 : 0);
        bool valid = fg && (n_pos > 0);
        float lossi = -logf((Fex + EPSF) / (Tex + 2.0f * EPSF));
        float w = valid ? iouw : 0.f;

        float sii_c = scl * TAU_INV;
        float Eex = E - __expf(sii_c);
        float SPex = SP - ((l > 0) ? sii_c : 0.f);
        float npc = (l > 0) ? (float)g_cnt[l] : 0.f;
        float dg = (l > 0) ? 1.f : 0.f;
        float L = logf(Eex);
        float slp = dg * NEGV + SPex - (npc - dg) * L;
        bool validc = fg && (npc > 0.f) && isfinite(L);
        float Lzi = validc ? (-slp / (npc + EPSF)) : 0.f;
        float wcv = validc ? iouw : 0.f;

        red[wid][0] = (double)w * (double)lossi;
        red[wid][1] = (double)w;
        red[wid][2] = (double)wcv * (double)Lzi;
        red[wid][3] = (double)wcv;
    }
    __syncthreads();
    if (threadIdx.x == 0) {
        double s0 = 0, s1 = 0, s2 = 0, s3 = 0;
#pragma unroll
        for (int i = 0; i < 8; ++i) {
            s0 += red[i][0]; s1 += red[i][1];
            s2 += red[i][2]; s3 += red[i][3];
        }
        g_bred[blockIdx.x * 4 + 0] = s0;
        g_bred[blockIdx.x * 4 + 1] = s1;
        g_bred[blockIdx.x * 4 + 2] = s2;
        g_bred[blockIdx.x * 4 + 3] = s3;
    }
}

__global__ void final_kernel(float* __restrict__ out) {
    __shared__ double sh[256][4];
    double a[4] = {0, 0, 0, 0};
    for (int b = threadIdx.x; b < NROWS / 8; b += 256) {
#pragma unroll
        for (int c = 0; c < 4; ++c) a[c] += g_bred[b * 4 + c];
    }
#pragma unroll
    for (int c = 0; c < 4; ++c) sh[threadIdx.x][c] = a[c];
    __syncthreads();
    for (int s = 128; s > 0; s >>= 1) {
        if (threadIdx.x < s) {
#pragma unroll
            for (int c = 0; c < 4; ++c) sh[threadIdx.x][c] += sh[threadIdx.x + s][c];
        }
        __syncthreads();
    }
    if (threadIdx.x == 0) {
        out[0] = (float)(sh[0][0] / (sh[0][1] + (double)EPSF));
        out[1] = (float)(sh[0][2] / (sh[0][3] + (double)EPSF));
    }
}

extern "C" void kernel_launch(void* const* d_in, const int* in_sizes, int n_in,
                              void* d_out, int out_size) {
    const float* roi   = (const float*)d_in[0];
    const int*   labw  = (const int*)d_in[1];
    const float* ious  = (const float*)d_in[2];
    const float* fg_w1 = (const float*)d_in[3];
    const float* fg_b1 = (const float*)d_in[4];
    const float* fg_w2 = (const float*)d_in[5];
    const float* fg_b2 = (const float*)d_in[6];
    const float* cl_w1 = (const float*)d_in[7];
    const float* cl_b1 = (const float*)d_in[8];
    const float* cl_w2 = (const float*)d_in[9];
    const float* cl_b2 = (const float*)d_in[10];
    float* out = (float*)d_out;

    static bool init = false;
    if (!init) {
        cudaFuncSetAttribute(sim_both, cudaFuncAttributeMaxDynamicSharedMemorySize, 100000);
        init = true;
    }

    prep_kernel<<<1, 256>>>(labw);
    gemm1_dual<<<dim3(NROWS / 128, HDIM / 64, 2), 256>>>(roi, fg_w1, fg_b1, cl_w1, cl_b1);
    gemm2_fused<<<dim3(NROWS / 128, 2), 256>>>(fg_w2, fg_b2, cl_w2, cl_b2);

    size_t smem_sim = (2 * 64 * PAD + 2 * 128) * sizeof(float);
    sim_both<<<2 * NPAIRS, 256, smem_sim>>>();

    rowfinal_kernel<<<NROWS / 8, 256>>>(ious);
    final_kernel<<<1, 256>>>(out);
}

// round 16
// speedup vs baseline: 1.4110x; 1.2978x over previous
#include <cuda_runtime.h>
#include <cuda_bf16.h>
#include <math.h>
#include <stdint.h>

#define NROWS 8192
#define CDIM  1024
#define HDIM  256
#define DFG   64
#define DCLS  128
#define NT    64
#define NPAIRS 2080
#define TAU_INV 5.0f
#define EPSF 1e-8f
#define NEGV (-1e9f)

typedef unsigned long long u64;

__device__ __forceinline__ u64 bcast2(float v) {
    u64 r; asm("mov.b64 %0, {%1, %1};" : "=l"(r) : "f"(v)); return r;
}
__device__ __forceinline__ void fma2(u64& d, u64 a, u64 b) {
    asm("fma.rn.f32x2 %0, %1, %2, %0;" : "+l"(d) : "l"(a), "l"(b));
}
__device__ __forceinline__ float2 unpack2(u64 v) {
    float2 r; asm("mov.b64 {%0, %1}, %2;" : "=f"(r.x), "=f"(r.y) : "l"(v)); return r;
}

__device__ float  g_h[NROWS * HDIM];
__device__ float  g_h2[NROWS * HDIM];
__device__ float  g_zfg[NROWS * DFG];
__device__ float  g_zcls[NROWS * DCLS];
__device__ __nv_bfloat16 g_zfg_h[NROWS * DFG];
__device__ __nv_bfloat16 g_zfg_l[NROWS * DFG];
__device__ __nv_bfloat16 g_zcls_h[NROWS * DCLS];
__device__ __nv_bfloat16 g_zcls_l[NROWS * DCLS];
__device__ float  g_T[NT * NROWS];
__device__ float  g_F[NT * NROWS];
__device__ float  g_E[NT * NROWS];
__device__ float  g_SP[NT * NROWS];
__device__ double g_bred[(NROWS / 8) * 4];
__device__ int    g_cnt[32];
__device__ int    g_lab[NROWS];

__device__ __forceinline__ uint32_t s2u(const void* p) {
    uint32_t a;
    asm("{ .reg .u64 t; cvta.to.shared.u64 t, %1; cvt.u32.u64 %0, t; }" : "=r"(a) : "l"(p));
    return a;
}
__device__ __forceinline__ void ldm4(uint32_t* r, uint32_t a) {
    asm volatile("ldmatrix.sync.aligned.m8n8.x4.shared.b16 {%0,%1,%2,%3}, [%4];"
                 : "=r"(r[0]), "=r"(r[1]), "=r"(r[2]), "=r"(r[3]) : "r"(a));
}
__device__ __forceinline__ void ldm2(uint32_t* r, uint32_t a) {
    asm volatile("ldmatrix.sync.aligned.m8n8.x2.shared.b16 {%0,%1}, [%2];"
                 : "=r"(r[0]), "=r"(r[1]) : "r"(a));
}
__device__ __forceinline__ void mmabf(float* d, const uint32_t* a, const uint32_t* b) {
    asm volatile("mma.sync.aligned.m16n8k16.row.col.f32.bf16.bf16.f32 "
                 "{%0,%1,%2,%3},{%4,%5,%6,%7},{%8,%9},{%0,%1,%2,%3};"
                 : "+f"(d[0]), "+f"(d[1]), "+f"(d[2]), "+f"(d[3])
                 : "r"(a[0]), "r"(a[1]), "r"(a[2]), "r"(a[3]), "r"(b[0]), "r"(b[1]));
}

#define PADB 72
#define TILEB (128 * PADB * 2)  // 18432 bytes per bf16 tile
#define OFF_AH 0
#define OFF_AL TILEB
#define OFF_BH (2 * TILEB)
#define OFF_BL (3 * TILEB)
#define OFF_LAB (4 * TILEB)      // labI[128], labJ[128], fgI[128], fgJ[128]
#define SMEM_SIM (4 * TILEB + 2048)
// epilogue aliases (tiles dead): rowT[2][128], rowF[2][128], colE[4][128], colS[4][128]
#define EOFF_ROWT 0
#define EOFF_ROWF 1024
#define EOFF_COLE 2048
#define EOFF_COLS 4096

__global__ void prep_kernel(const int* __restrict__ w) {
    __shared__ int s;
    __shared__ int cnt[32];
    if (threadIdx.x == 0) s = 0;
    if (threadIdx.x < 32) cnt[threadIdx.x] = 0;
    __syncthreads();
    int local = 0;
    for (int i = threadIdx.x; i < NROWS / 2; i += 256)
        if (w[2 * i + 1] != 0) local = 1;
    if (local) atomicOr(&s, 1);
    __syncthreads();
    const int is32 = s;
    for (int i = threadIdx.x; i < NROWS; i += 256) {
        int l = is32 ? w[i] : w[2 * i];
        g_lab[i] = l;
        if (l >= 0 && l < 32) atomicAdd(&cnt[l], 1);
    }
    __syncthreads();
    if (threadIdx.x < 32) g_cnt[threadIdx.x] = cnt[threadIdx.x];
}

__device__ __forceinline__ void gemm_tile_relu(const float* __restrict__ A,
                                               const float* __restrict__ B,
                                               const float* __restrict__ bias,
                                               float* __restrict__ C,
                                               int N, int K, int row0, int col0) {
    __shared__ float As[2][16][132];
    __shared__ float Bs[2][16][68];
    const int tid = threadIdx.x;
    const int ty = tid >> 4, tx = tid & 15;
    const int mA = tid >> 2, kA = (tid & 3) << 2;
    const int kB = tid >> 4, nB = (tid & 15) << 2;
    u64 acc2[4][4];
#pragma unroll
    for (int i = 0; i < 4; ++i)
#pragma unroll
        for (int j = 0; j < 4; ++j) acc2[i][j] = 0ull;

    const float* pA0 = A + (size_t)(row0 + mA) * K + kA;
    const float* pA1 = A + (size_t)(row0 + mA + 64) * K + kA;
    const float* pB = B + (size_t)kB * N + col0 + nB;

    float4 ra0 = *(const float4*)pA0;
    float4 ra1 = *(const float4*)pA1;
    float4 rb = *(const float4*)pB;
    As[0][kA + 0][mA] = ra0.x; As[0][kA + 1][mA] = ra0.y;
    As[0][kA + 2][mA] = ra0.z; As[0][kA + 3][mA] = ra0.w;
    As[0][kA + 0][mA + 64] = ra1.x; As[0][kA + 1][mA + 64] = ra1.y;
    As[0][kA + 2][mA + 64] = ra1.z; As[0][kA + 3][mA + 64] = ra1.w;
    *(float4*)&Bs[0][kB][nB] = rb;
    __syncthreads();

    const int TI = K >> 4;
    for (int t = 0; t < TI; ++t) {
        const int cur = t & 1;
        if (t + 1 < TI) {
            const int k0 = (t + 1) << 4;
            ra0 = *(const float4*)(pA0 + k0);
            ra1 = *(const float4*)(pA1 + k0);
            rb = *(const float4*)(pB + (size_t)k0 * N);
        }
#pragma unroll
        for (int kk = 0; kk < 16; ++kk) {
            const float* ar = &As[cur][kk][ty * 8];
            ulonglong2 a01 = *(const ulonglong2*)ar;
            ulonglong2 a23 = *(const ulonglong2*)(ar + 4);
            u64 pa[4] = {a01.x, a01.y, a23.x, a23.y};
            float4 b = *(const float4*)&Bs[cur][kk][tx * 4];
            u64 pb[4] = {bcast2(b.x), bcast2(b.y), bcast2(b.z), bcast2(b.w)};
#pragma unroll
            for (int i = 0; i < 4; ++i)
#pragma unroll
                for (int j = 0; j < 4; ++j) fma2(acc2[i][j], pa[i], pb[j]);
        }
        if (t + 1 < TI) {
            const int nxt = cur ^ 1;
            As[nxt][kA + 0][mA] = ra0.x; As[nxt][kA + 1][mA] = ra0.y;
            As[nxt][kA + 2][mA] = ra0.z; As[nxt][kA + 3][mA] = ra0.w;
            As[nxt][kA + 0][mA + 64] = ra1.x; As[nxt][kA + 1][mA + 64] = ra1.y;
            As[nxt][kA + 2][mA + 64] = ra1.z; As[nxt][kA + 3][mA + 64] = ra1.w;
            *(float4*)&Bs[nxt][kB][nB] = rb;
        }
        __syncthreads();
    }
    float4 bb = *(const float4*)(bias + col0 + tx * 4);
    float bv[4] = {bb.x, bb.y, bb.z, bb.w};
#pragma unroll
    for (int i2 = 0; i2 < 4; ++i2) {
        float2 v0 = unpack2(acc2[i2][0]);
        float2 v1 = unpack2(acc2[i2][1]);
        float2 v2 = unpack2(acc2[i2][2]);
        float2 v3 = unpack2(acc2[i2][3]);
        float4 o0, o1;
        o0.x = fmaxf(v0.x + bv[0], 0.f); o0.y = fmaxf(v1.x + bv[1], 0.f);
        o0.z = fmaxf(v2.x + bv[2], 0.f); o0.w = fmaxf(v3.x + bv[3], 0.f);
        o1.x = fmaxf(v0.y + bv[0], 0.f); o1.y = fmaxf(v1.y + bv[1], 0.f);
        o1.z = fmaxf(v2.y + bv[2], 0.f); o1.w = fmaxf(v3.y + bv[3], 0.f);
        *(float4*)(C + (size_t)(row0 + ty * 8 + 2 * i2) * N + col0 + tx * 4) = o0;
        *(float4*)(C + (size_t)(row0 + ty * 8 + 2 * i2 + 1) * N + col0 + tx * 4) = o1;
    }
}

__global__ void __launch_bounds__(256, 3) gemm1_dual(const float* __restrict__ A,
                                                     const float* __restrict__ B0,
                                                     const float* __restrict__ b0,
                                                     const float* __restrict__ B1,
                                                     const float* __restrict__ b1) {
    const float* B = blockIdx.z ? B1 : B0;
    const float* bias = blockIdx.z ? b1 : b0;
    float* C = blockIdx.z ? g_h2 : g_h;
    gemm_tile_relu(A, B, bias, C, HDIM, CDIM, blockIdx.x * 128, blockIdx.y * 64);
}

__global__ void __launch_bounds__(256) gemm2_fused(const float* __restrict__ Bf,
                                                   const float* __restrict__ bf,
                                                   const float* __restrict__ Bc,
                                                   const float* __restrict__ bc) {
    __shared__ float As[2][16][132];
    __shared__ float Bs[2][16][132];
    const int tid = threadIdx.x;
    const int ty = tid >> 4, tx = tid & 15;
    const int mA = tid >> 2, kA = (tid & 3) << 2;
    const int row0 = blockIdx.x * 128;
    const int TI = HDIM >> 4;

    if (blockIdx.y == 0) {
        const int kB = tid >> 4, nB = (tid & 15) << 2;
        u64 acc2[4][4];
#pragma unroll
        for (int i = 0; i < 4; ++i)
#pragma unroll
            for (int j = 0; j < 4; ++j) acc2[i][j] = 0ull;
        const float* pA0 = g_h + (size_t)(row0 + mA) * HDIM + kA;
        const float* pA1 = g_h + (size_t)(row0 + mA + 64) * HDIM + kA;
        const float* pB = Bf + (size_t)kB * DFG + nB;
        float4 ra0 = *(const float4*)pA0;
        float4 ra1 = *(const float4*)pA1;
        float4 rb = *(const float4*)pB;
        As[0][kA + 0][mA] = ra0.x; As[0][kA + 1][mA] = ra0.y;
        As[0][kA + 2][mA] = ra0.z; As[0][kA + 3][mA] = ra0.w;
        As[0][kA + 0][mA + 64] = ra1.x; As[0][kA + 1][mA + 64] = ra1.y;
        As[0][kA + 2][mA + 64] = ra1.z; As[0][kA + 3][mA + 64] = ra1.w;
        *(float4*)&Bs[0][kB][nB] = rb;
        __syncthreads();
        for (int t = 0; t < TI; ++t) {
            const int cur = t & 1;
            if (t + 1 < TI) {
                const int k0 = (t + 1) << 4;
                ra0 = *(const float4*)(pA0 + k0);
                ra1 = *(const float4*)(pA1 + k0);
                rb = *(const float4*)(pB + (size_t)k0 * DFG);
            }
#pragma unroll
            for (int kk = 0; kk < 16; ++kk) {
                const float* ar = &As[cur][kk][ty * 8];
                ulonglong2 a01 = *(const ulonglong2*)ar;
                ulonglong2 a23 = *(const ulonglong2*)(ar + 4);
                u64 pa[4] = {a01.x, a01.y, a23.x, a23.y};
                float4 b = *(const float4*)&Bs[cur][kk][tx * 4];
                u64 pb[4] = {bcast2(b.x), bcast2(b.y), bcast2(b.z), bcast2(b.w)};
#pragma unroll
                for (int i = 0; i < 4; ++i)
#pragma unroll
                    for (int j = 0; j < 4; ++j) fma2(acc2[i][j], pa[i], pb[j]);
            }
            if (t + 1 < TI) {
                const int nxt = cur ^ 1;
                As[nxt][kA + 0][mA] = ra0.x; As[nxt][kA + 1][mA] = ra0.y;
                As[nxt][kA + 2][mA] = ra0.z; As[nxt][kA + 3][mA] = ra0.w;
                As[nxt][kA + 0][mA + 64] = ra1.x; As[nxt][kA + 1][mA + 64] = ra1.y;
                As[nxt][kA + 2][mA + 64] = ra1.z; As[nxt][kA + 3][mA + 64] = ra1.w;
                *(float4*)&Bs[nxt][kB][nB] = rb;
            }
            __syncthreads();
        }
        float4 bb = *(const float4*)(bf + tx * 4);
        float bv[4] = {bb.x, bb.y, bb.z, bb.w};
        float v[8][4];
#pragma unroll
        for (int i2 = 0; i2 < 4; ++i2)
#pragma unroll
            for (int j = 0; j < 4; ++j) {
                float2 p = unpack2(acc2[i2][j]);
                v[2 * i2][j] = p.x + bv[j];
                v[2 * i2 + 1][j] = p.y + bv[j];
            }
#pragma unroll
        for (int r = 0; r < 8; ++r) {
            float s = v[r][0] * v[r][0] + v[r][1] * v[r][1] +
                      v[r][2] * v[r][2] + v[r][3] * v[r][3];
#pragma unroll
            for (int off = 8; off > 0; off >>= 1) s += __shfl_xor_sync(0xffffffffu, s, off, 16);
            float inv = 1.f / fmaxf(sqrtf(s), EPSF);
            float4 o;
            o.x = v[r][0] * inv; o.y = v[r][1] * inv;
            o.z = v[r][2] * inv; o.w = v[r][3] * inv;
            *(float4*)(g_zfg + (size_t)(row0 + ty * 8 + r) * DFG + tx * 4) = o;
        }
    } else {
        const int kB = tid >> 4, nB = (tid & 15) << 3;
        u64 acc2[4][8];
#pragma unroll
        for (int i = 0; i < 4; ++i)
#pragma unroll
            for (int j = 0; j < 8; ++j) acc2[i][j] = 0ull;
        const float* pA0 = g_h2 + (size_t)(row0 + mA) * HDIM + kA;
        const float* pA1 = g_h2 + (size_t)(row0 + mA + 64) * HDIM + kA;
        const float* pB = Bc + (size_t)kB * DCLS + nB;
        float4 ra0 = *(const float4*)pA0;
        float4 ra1 = *(const float4*)pA1;
        float4 rb0 = *(const float4*)pB;
        float4 rb1 = *(const float4*)(pB + 4);
        As[0][kA + 0][mA] = ra0.x; As[0][kA + 1][mA] = ra0.y;
        As[0][kA + 2][mA] = ra0.z; As[0][kA + 3][mA] = ra0.w;
        As[0][kA + 0][mA + 64] = ra1.x; As[0][kA + 1][mA + 64] = ra1.y;
        As[0][kA + 2][mA + 64] = ra1.z; As[0][kA + 3][mA + 64] = ra1.w;
        *(float4*)&Bs[0][kB][nB] = rb0;
        *(float4*)&Bs[0][kB][nB + 4] = rb1;
        __syncthreads();
        for (int t = 0; t < TI; ++t) {
            const int cur = t & 1;
            if (t + 1 < TI) {
                const int k0 = (t + 1) << 4;
                ra0 = *(const float4*)(pA0 + k0);
                ra1 = *(const float4*)(pA1 + k0);
                rb0 = *(const float4*)(pB + (size_t)k0 * DCLS);
                rb1 = *(const float4*)(pB + (size_t)k0 * DCLS + 4);
            }
#pragma unroll
            for (int kk = 0; kk < 16; ++kk) {
                const float* ar = &As[cur][kk][ty * 8];
                ulonglong2 a01 = *(const ulonglong2*)ar;
                ulonglong2 a23 = *(const ulonglong2*)(ar + 4);
                u64 pa[4] = {a01.x, a01.y, a23.x, a23.y};
                float4 b0 = *(const float4*)&Bs[cur][kk][tx * 4];
                float4 b1 = *(const float4*)&Bs[cur][kk][64 + tx * 4];
                u64 pb[8] = {bcast2(b0.x), bcast2(b0.y), bcast2(b0.z), bcast2(b0.w),
                             bcast2(b1.x), bcast2(b1.y), bcast2(b1.z), bcast2(b1.w)};
#pragma unroll
                for (int i = 0; i < 4; ++i)
#pragma unroll
                    for (int j = 0; j < 8; ++j) fma2(acc2[i][j], pa[i], pb[j]);
            }
            if (t + 1 < TI) {
                const int nxt = cur ^ 1;
                As[nxt][kA + 0][mA] = ra0.x; As[nxt][kA + 1][mA] = ra0.y;
                As[nxt][kA + 2][mA] = ra0.z; As[nxt][kA + 3][mA] = ra0.w;
                As[nxt][kA + 0][mA + 64] = ra1.x; As[nxt][kA + 1][mA + 64] = ra1.y;
                As[nxt][kA + 2][mA + 64] = ra1.z; As[nxt][kA + 3][mA + 64] = ra1.w;
                *(float4*)&Bs[nxt][kB][nB] = rb0;
                *(float4*)&Bs[nxt][kB][nB + 4] = rb1;
            }
            __syncthreads();
        }
        float4 bb0 = *(const float4*)(bc + tx * 4);
        float4 bb1 = *(const float4*)(bc + 64 + tx * 4);
        float bv[8] = {bb0.x, bb0.y, bb0.z, bb0.w, bb1.x, bb1.y, bb1.z, bb1.w};
        float v[8][8];
#pragma unroll
        for (int i2 = 0; i2 < 4; ++i2)
#pragma unroll
            for (int j = 0; j < 8; ++j) {
                float2 p = unpack2(acc2[i2][j]);
                v[2 * i2][j] = p.x + bv[j];
                v[2 * i2 + 1][j] = p.y + bv[j];
            }
#pragma unroll
        for (int r = 0; r < 8; ++r) {
            float s = 0.f;
#pragma unroll
            for (int j = 0; j < 8; ++j) s += v[r][j] * v[r][j];
#pragma unroll
            for (int off = 8; off > 0; off >>= 1) s += __shfl_xor_sync(0xffffffffu, s, off, 16);
            float inv = 1.f / fmaxf(sqrtf(s), EPSF);
            float4 o0, o1;
            o0.x = v[r][0] * inv; o0.y = v[r][1] * inv;
            o0.z = v[r][2] * inv; o0.w = v[r][3] * inv;
            o1.x = v[r][4] * inv; o1.y = v[r][5] * inv;
            o1.z = v[r][6] * inv; o1.w = v[r][7] * inv;
            *(float4*)(g_zcls + (size_t)(row0 + ty * 8 + r) * DCLS + tx * 4) = o0;
            *(float4*)(g_zcls + (size_t)(row0 + ty * 8 + r) * DCLS + 64 + tx * 4) = o1;
        }
    }
}

__global__ void convert_kernel() {
    const int stride = gridDim.x * blockDim.x;
    int g = blockIdx.x * blockDim.x + threadIdx.x;
    for (int i = g; i < NROWS * DFG; i += stride) {
        float z = g_zfg[i];
        __nv_bfloat16 h = __float2bfloat16(z);
        g_zfg_h[i] = h;
        g_zfg_l[i] = __float2bfloat16(z - __bfloat162float(h));
    }
    for (int i = g; i < NROWS * DCLS; i += stride) {
        float z = g_zcls[i];
        __nv_bfloat16 h = __float2bfloat16(z);
        g_zcls_h[i] = h;
        g_zcls_l[i] = __float2bfloat16(z - __bfloat162float(h));
    }
}

__device__ __forceinline__ void decode_pair(int t, int& I, int& J) {
    int i = (int)((129.0f - sqrtf(16641.0f - 8.0f * (float)t)) * 0.5f);
    if (i < 0) i = 0;
    if (i > NT - 1) i = NT - 1;
    while (i * (129 - i) / 2 > t) --i;
    while ((i + 1) * (128 - i) / 2 <= t) ++i;
    I = i;
    J = i + (t - i * (129 - i) / 2);
}

// mma.sync sim: 256 thr, 128x128 tile; warp w -> rows 32*(w>>1), cols 64*(w&1)
__global__ void __launch_bounds__(256, 2) sim_mma() {
    extern __shared__ __align__(16) unsigned char smx[];
    const uint32_t sb = s2u(smx);
    const int tid = threadIdx.x;
    const int wid = tid >> 5, lane = tid & 31;
    const bool cls = blockIdx.x < NPAIRS;
    const int pidx = cls ? blockIdx.x : blockIdx.x - NPAIRS;
    int I, J;
    decode_pair(pidx, I, J);
    const int row0 = I * 128, col0 = J * 128;
    const bool diag = (I == J);
    const int Dtot = cls ? DCLS : DFG;
    const int nch = cls ? 2 : 1;
    const __nv_bfloat16* zh = cls ? g_zcls_h : g_zfg_h;
    const __nv_bfloat16* zl = cls ? g_zcls_l : g_zfg_l;

    int* labI = (int*)(smx + OFF_LAB);
    int* labJ = labI + 128;
    float* fgI = (float*)(labJ + 128);
    float* fgJ = fgI + 128;
    if (tid < 128) {
        int li = g_lab[row0 + tid], lj = g_lab[col0 + tid];
        labI[tid] = li; labJ[tid] = lj;
        fgI[tid] = (li > 0) ? 1.f : 0.f;
        fgJ[tid] = (lj > 0) ? 1.f : 0.f;
    }

    const int wq = wid >> 1, wh = wid & 1;
    const int mr0 = wq * 32, nc0 = wh * 64;
    float acc[2][8][4];
#pragma unroll
    for (int m = 0; m < 2; ++m)
#pragma unroll
        for (int n = 0; n < 8; ++n)
#pragma unroll
            for (int c = 0; c < 4; ++c) acc[m][n][c] = 0.f;

    const int l15 = lane & 15;
    for (int ch = 0; ch < nch; ++ch) {
        __syncthreads();
        // load 4 tiles [128][64] bf16 into [128][PADB]
#pragma unroll
        for (int m = 0; m < 4; ++m) {
            const __nv_bfloat16* src =
                ((m & 1) ? zl : zh) + (size_t)((m < 2) ? row0 : col0) * Dtot + ch * 64;
            __nv_bfloat16* dst = (__nv_bfloat16*)(smx + ((m < 2) ? (m ? OFF_AL : OFF_AH)
                                                                 : (m == 2 ? OFF_BH : OFF_BL)));
            for (int u = tid; u < 1024; u += 256) {
                int r = u >> 3, c8 = u & 7;
                uint4 v = *(const uint4*)(src + (size_t)r * Dtot + c8 * 8);
                *(uint4*)(dst + r * PADB + c8 * 8) = v;
            }
        }
        __syncthreads();
#pragma unroll
        for (int ks = 0; ks < 4; ++ks) {
            const int kb = ks * 16;
            uint32_t ah[2][4], al[2][4];
#pragma unroll
            for (int mt = 0; mt < 2; ++mt) {
                int arow = mr0 + mt * 16 + l15;
                int akk = kb + (lane >> 4) * 8;
                uint32_t off = (uint32_t)(arow * PADB + akk) * 2;
                ldm4(ah[mt], sb + OFF_AH + off);
                ldm4(al[mt], sb + OFF_AL + off);
            }
#pragma unroll
            for (int nt = 0; nt < 8; ++nt) {
                int brow = nc0 + nt * 8 + (l15 & 7);
                int bkk = kb + ((l15 >> 3) & 1) * 8;
                uint32_t off = (uint32_t)(brow * PADB + bkk) * 2;
                uint32_t bh[2], bl[2];
                ldm2(bh, sb + OFF_BH + off);
                ldm2(bl, sb + OFF_BL + off);
#pragma unroll
                for (int mt = 0; mt < 2; ++mt) {
                    mmabf(acc[mt][nt], ah[mt], bh);
                    mmabf(acc[mt][nt], ah[mt], bl);
                    mmabf(acc[mt][nt], al[mt], bh);
                }
            }
        }
    }
    __syncthreads();  // tiles dead; epilogue buffers alias

    float* rowT = (float*)(smx + EOFF_ROWT);  // [2][128]
    float* rowF = (float*)(smx + EOFF_ROWF);
    float* colE = (float*)(smx + EOFF_COLE);  // [4][128]
    float* colS = (float*)(smx + EOFF_COLS);
    const int tq = lane >> 2, tr = lane & 3;

    float colPE[8][2], colPS[8][2];
#pragma unroll
    for (int n = 0; n < 8; ++n) { colPE[n][0] = colPE[n][1] = 0.f; colPS[n][0] = colPS[n][1] = 0.f; }

#pragma unroll
    for (int mt = 0; mt < 2; ++mt) {
        const int r0 = mr0 + mt * 16 + tq, r1 = r0 + 8;
        const int lab0 = labI[r0], lab1 = labI[r1];
        const float fg0 = fgI[r0], fg1 = fgI[r1];
        float rA0 = 0.f, rB0 = 0.f, rA1 = 0.f, rB1 = 0.f;
#pragma unroll
        for (int n = 0; n < 8; ++n) {
            const int c0 = nc0 + n * 8 + tr * 2, c1 = c0 + 1;
            float s00 = acc[mt][n][0] * TAU_INV, s01 = acc[mt][n][1] * TAU_INV;
            float s10 = acc[mt][n][2] * TAU_INV, s11 = acc[mt][n][3] * TAU_INV;
            float e00 = __expf(s00), e01 = __expf(s01);
            float e10 = __expf(s10), e11 = __expf(s11);
            rA0 += e00 + e01; rA1 += e10 + e11;
            colPE[n][0] += e00 + e10; colPE[n][1] += e01 + e11;
            if (cls) {
                int lc0 = labJ[c0], lc1 = labJ[c1];
                if (lc0 > 0) {
                    if (lc0 == lab0) rB0 += s00;
                    if (lc0 == lab1) rB1 += s10;
                    float t = ((lc0 == lab0) ? s00 : 0.f) + ((lc0 == lab1) ? s10 : 0.f);
                    colPS[n][0] += t;
                }
                if (lc1 > 0) {
                    if (lc1 == lab0) rB0 += s01;
                    if (lc1 == lab1) rB1 += s11;
                    float t = ((lc1 == lab0) ? s01 : 0.f) + ((lc1 == lab1) ? s11 : 0.f);
                    colPS[n][1] += t;
                }
            } else {
                float fj0 = fgJ[c0], fj1 = fgJ[c1];
                rB0 += e00 * fj0 + e01 * fj1;
                rB1 += e10 * fj0 + e11 * fj1;
                colPS[n][0] += e00 * fg0 + e10 * fg1;
                colPS[n][1] += e01 * fg0 + e11 * fg1;
            }
        }
        // row reduce across tr (lanes bits 0-1)
        rA0 += __shfl_xor_sync(0xffffffffu, rA0, 1);
        rA0 += __shfl_xor_sync(0xffffffffu, rA0, 2);
        rB0 += __shfl_xor_sync(0xffffffffu, rB0, 1);
        rB0 += __shfl_xor_sync(0xffffffffu, rB0, 2);
        rA1 += __shfl_xor_sync(0xffffffffu, rA1, 1);
        rA1 += __shfl_xor_sync(0xffffffffu, rA1, 2);
        rB1 += __shfl_xor_sync(0xffffffffu, rB1, 1);
        rB1 += __shfl_xor_sync(0xffffffffu, rB1, 2);
        if (tr == 0) {
            rowT[wh * 128 + r0] = rA0; rowF[wh * 128 + r0] = rB0;
            rowT[wh * 128 + r1] = rA1; rowF[wh * 128 + r1] = rB1;
        }
    }
    // col reduce across tq (lane bits 2-4)
#pragma unroll
    for (int n = 0; n < 8; ++n) {
#pragma unroll
        for (int h = 0; h < 2; ++h) {
            float e = colPE[n][h], s = colPS[n][h];
            e += __shfl_xor_sync(0xffffffffu, e, 4);
            e += __shfl_xor_sync(0xffffffffu, e, 8);
            e += __shfl_xor_sync(0xffffffffu, e, 16);
            s += __shfl_xor_sync(0xffffffffu, s, 4);
            s += __shfl_xor_sync(0xffffffffu, s, 8);
            s += __shfl_xor_sync(0xffffffffu, s, 16);
            if (tq == 0) {
                int c = nc0 + n * 8 + tr * 2 + h;
                colE[wq * 128 + c] = e;
                colS[wq * 128 + c] = s;
            }
        }
    }
    __syncthreads();
    if (tid < 128) {
        float rA = rowT[tid] + rowT[128 + tid];
        float rB = rowF[tid] + rowF[128 + tid];
        if (cls) {
            g_E[(size_t)J * NROWS + row0 + tid] = rA;
            g_SP[(size_t)J * NROWS + row0 + tid] = rB;
        } else {
            g_T[(size_t)J * NROWS + row0 + tid] = rA;
            g_F[(size_t)J * NROWS + row0 + tid] = rB;
        }
        if (!diag) {
            float cE = colE[tid] + colE[128 + tid] + colE[256 + tid] + colE[384 + tid];
            float cS = colS[tid] + colS[128 + tid] + colS[256 + tid] + colS[384 + tid];
            if (cls) {
                g_E[(size_t)I * NROWS + col0 + tid] = cE;
                g_SP[(size_t)I * NROWS + col0 + tid] = cS;
            } else {
                g_T[(size_t)I * NROWS + col0 + tid] = cE;
                g_F[(size_t)I * NROWS + col0 + tid] = cS;
            }
        }
    }
}

__global__ void __launch_bounds__(256) rowfinal_kernel(const float* __restrict__ ious) {
    const int wid = threadIdx.x >> 5, lane = threadIdx.x & 31;
    const int row = blockIdx.x * 8 + wid;

    float T = 0.f, F = 0.f, E = 0.f, SP = 0.f;
#pragma unroll
    for (int s = lane; s < NT; s += 32) {
        T += g_T[(size_t)s * NROWS + row];
        F += g_F[(size_t)s * NROWS + row];
        E += g_E[(size_t)s * NROWS + row];
        SP += g_SP[(size_t)s * NROWS + row];
    }
#pragma unroll
    for (int off = 16; off > 0; off >>= 1) {
        T += __shfl_xor_sync(0xffffffffu, T, off);
        F += __shfl_xor_sync(0xffffffffu, F, off);
        E += __shfl_xor_sync(0xffffffffu, E, off);
        SP += __shfl_xor_sync(0xffffffffu, SP, off);
    }
    float sfg = 0.f;
    for (int d = lane; d < DFG; d += 32) {
        float v = g_zfg[(size_t)row * DFG + d];
        sfg += v * v;
    }
    float scl = 0.f;
    for (int d = lane; d < DCLS; d += 32) {
        float v = g_zcls[(size_t)row * DCLS + d];
        scl += v * v;
    }
#pragma unroll
    for (int off = 16; off > 0; off >>= 1) {
        sfg += __shfl_xor_sync(0xffffffffu, sfg, off);
        scl += __shfl_xor_sync(0xffffffffu, scl, off);
    }

    __shared__ double red[8][4];
    if (lane == 0) {
        int l = g_lab[row];
        bool fg = (l > 0);
        float iou = ious[row];
        float iouw = (iou > 0.5f) ? iou : 0.f;

        // diagonal of bf16-split sim: hi*hi + hi*lo + lo*hi of z_i . z_i
        float hh = 0.f, hl2 = 0.f;
        if (true) {
            const __nv_bfloat16* zh = g_zfg_h + (size_t)row * DFG;
            const __nv_bfloat16* zl = g_zfg_l + (size_t)row * DFG;
            // recompute in lane 0 only: D small
            for (int d = 0; d < DFG; ++d) {
                float h = __bfloat162float(zh[d]), lo = __bfloat162float(zl[d]);
                hh += h * h;
                hl2 += 2.f * h * lo;
            }
        }
        float eii = __expf((hh + hl2) * TAU_INV);
        float Tex = T - eii;
        float Fex = F - (fg ? eii : 0.f);
        int nfg = NROWS - g_cnt[0];
        int n_pos = nfg - (fg ? 1 : 0);
        bool valid = fg && (n_pos > 0);
        float lossi = -logf((Fex + EPSF) / (Tex + 2.0f * EPSF));
        float w = valid ? iouw : 0.f;

        float chh = 0.f, chl = 0.f;
        {
            const __nv_bfloat16* zh = g_zcls_h + (size_t)row * DCLS;
            const __nv_bfloat16* zl = g_zcls_l + (size_t)row * DCLS;
            for (int d = 0; d < DCLS; ++d) {
                float h = __bfloat162float(zh[d]), lo = __bfloat162float(zl[d]);
                chh += h * h;
                chl += 2.f * h * lo;
            }
        }
        float sii_c = (chh + chl) * TAU_INV;
        float Eex = E - __expf(sii_c);
        float SPex = SP - ((l > 0) ? sii_c : 0.f);
        float npc = (l > 0) ? (float)g_cnt[l] : 0.f;
        float dg = (l > 0) ? 1.f : 0.f;
        float L = logf(Eex);
        float slp = dg * NEGV + SPex - (npc - dg) * L;
        bool validc = fg && (npc > 0.f) && isfinite(L);
        float Lzi = validc ? (-slp / (npc + EPSF)) : 0.f;
        float wcv = validc ? iouw : 0.f;

        red[wid][0] = (double)w * (double)lossi;
        red[wid][1] = (double)w;
        red[wid][2] = (double)wcv * (double)Lzi;
        red[wid][3] = (double)wcv;
    }
    __syncthreads();
    if (threadIdx.x == 0) {
        double s0 = 0, s1 = 0, s2 = 0, s3 = 0;
#pragma unroll
        for (int i = 0; i < 8; ++i) {
            s0 += red[i][0]; s1 += red[i][1];
            s2 += red[i][2]; s3 += red[i][3];
        }
        g_bred[blockIdx.x * 4 + 0] = s0;
        g_bred[blockIdx.x * 4 + 1] = s1;
        g_bred[blockIdx.x * 4 + 2] = s2;
        g_bred[blockIdx.x * 4 + 3] = s3;
    }
}

__global__ void final_kernel(float* __restrict__ out) {
    __shared__ double sh[256][4];
    double a[4] = {0, 0, 0, 0};
    for (int b = threadIdx.x; b < NROWS / 8; b += 256) {
#pragma unroll
        for (int c = 0; c < 4; ++c) a[c] += g_bred[b * 4 + c];
    }
#pragma unroll
    for (int c = 0; c < 4; ++c) sh[threadIdx.x][c] = a[c];
    __syncthreads();
    for (int s = 128; s > 0; s >>= 1) {
        if (threadIdx.x < s) {
#pragma unroll
            for (int c = 0; c < 4; ++c) sh[threadIdx.x][c] += sh[threadIdx.x + s][c];
        }
        __syncthreads();
    }
    if (threadIdx.x == 0) {
        out[0] = (float)(sh[0][0] / (sh[0][1] + (double)EPSF));
        out[1] = (float)(sh[0][2] / (sh[0][3] + (double)EPSF));
    }
}

extern "C" void kernel_launch(void* const* d_in, const int* in_sizes, int n_in,
                              void* d_out, int out_size) {
    const float* roi   = (const float*)d_in[0];
    const int*   labw  = (const int*)d_in[1];
    const float* ious  = (const float*)d_in[2];
    const float* fg_w1 = (const float*)d_in[3];
    const float* fg_b1 = (const float*)d_in[4];
    const float* fg_w2 = (const float*)d_in[5];
    const float* fg_b2 = (const float*)d_in[6];
    const float* cl_w1 = (const float*)d_in[7];
    const float* cl_b1 = (const float*)d_in[8];
    const float* cl_w2 = (const float*)d_in[9];
    const float* cl_b2 = (const float*)d_in[10];
    float* out = (float*)d_out;

    static bool init = false;
    if (!init) {
        cudaFuncSetAttribute(sim_mma, cudaFuncAttributeMaxDynamicSharedMemorySize, SMEM_SIM);
        init = true;
    }

    prep_kernel<<<1, 256>>>(labw);
    gemm1_dual<<<dim3(NROWS / 128, HDIM / 64, 2), 256>>>(roi, fg_w1, fg_b1, cl_w1, cl_b1);
    gemm2_fused<<<dim3(NROWS / 128, 2), 256>>>(fg_w2, fg_b2, cl_w2, cl_b2);
    convert_kernel<<<512, 256>>>();

    sim_mma<<<2 * NPAIRS, 256, SMEM_SIM>>>();

    rowfinal_kernel<<<NROWS / 8, 256>>>(ious);
    final_kernel<<<1, 256>>>(out);
}

// round 17
// speedup vs baseline: 1.5969x; 1.1318x over previous
#include <cuda_runtime.h>
#include <cuda_bf16.h>
#include <math.h>
#include <stdint.h>

#define NROWS 8192
#define CDIM  1024
#define HDIM  256
#define DFG   64
#define DCLS  128
#define NT    64
#define NPAIRS 2080
#define TAU_INV 5.0f
#define EPSF 1e-8f
#define NEGV (-1e9f)

typedef unsigned long long u64;

__device__ __forceinline__ u64 bcast2(float v) {
    u64 r; asm("mov.b64 %0, {%1, %1};" : "=l"(r) : "f"(v)); return r;
}
__device__ __forceinline__ void fma2(u64& d, u64 a, u64 b) {
    asm("fma.rn.f32x2 %0, %1, %2, %0;" : "+l"(d) : "l"(a), "l"(b));
}
__device__ __forceinline__ float2 unpack2(u64 v) {
    float2 r; asm("mov.b64 {%0, %1}, %2;" : "=f"(r.x), "=f"(r.y) : "l"(v)); return r;
}

__device__ float  g_h[NROWS * HDIM];
__device__ float  g_h2[NROWS * HDIM];
__device__ float  g_zfg[NROWS * DFG];
__device__ float  g_zcls[NROWS * DCLS];
__device__ __nv_bfloat16 g_roi_h[NROWS * CDIM];
__device__ __nv_bfloat16 g_roi_l[NROWS * CDIM];
__device__ __nv_bfloat16 g_w1t_h[2 * HDIM * CDIM];
__device__ __nv_bfloat16 g_w1t_l[2 * HDIM * CDIM];
__device__ __nv_bfloat16 g_zfg_h[NROWS * DFG];
__device__ __nv_bfloat16 g_zfg_l[NROWS * DFG];
__device__ __nv_bfloat16 g_zcls_h[NROWS * DCLS];
__device__ __nv_bfloat16 g_zcls_l[NROWS * DCLS];
__device__ float  g_T[NT * NROWS];
__device__ float  g_F[NT * NROWS];
__device__ float  g_E[NT * NROWS];
__device__ float  g_SP[NT * NROWS];
__device__ double g_bred[(NROWS / 8) * 4];
__device__ int    g_cnt[32];
__device__ int    g_lab[NROWS];

__device__ __forceinline__ uint32_t s2u(const void* p) {
    uint32_t a;
    asm("{ .reg .u64 t; cvta.to.shared.u64 t, %1; cvt.u32.u64 %0, t; }" : "=r"(a) : "l"(p));
    return a;
}
__device__ __forceinline__ void ldm4(uint32_t* r, uint32_t a) {
    asm volatile("ldmatrix.sync.aligned.m8n8.x4.shared.b16 {%0,%1,%2,%3}, [%4];"
                 : "=r"(r[0]), "=r"(r[1]), "=r"(r[2]), "=r"(r[3]) : "r"(a));
}
__device__ __forceinline__ void ldm2(uint32_t* r, uint32_t a) {
    asm volatile("ldmatrix.sync.aligned.m8n8.x2.shared.b16 {%0,%1}, [%2];"
                 : "=r"(r[0]), "=r"(r[1]) : "r"(a));
}
__device__ __forceinline__ void mmabf(float* d, const uint32_t* a, const uint32_t* b) {
    asm volatile("mma.sync.aligned.m16n8k16.row.col.f32.bf16.bf16.f32 "
                 "{%0,%1,%2,%3},{%4,%5,%6,%7},{%8,%9},{%0,%1,%2,%3};"
                 : "+f"(d[0]), "+f"(d[1]), "+f"(d[2]), "+f"(d[3])
                 : "r"(a[0]), "r"(a[1]), "r"(a[2]), "r"(a[3]), "r"(b[0]), "r"(b[1]));
}

#define PADB 72
#define TILEB (128 * PADB * 2)
#define OFF_AH 0
#define OFF_AL TILEB
#define OFF_BH (2 * TILEB)
#define OFF_BL (3 * TILEB)
#define OFF_LAB (4 * TILEB)
#define SMEM_SIM (4 * TILEB + 2048)
#define EOFF_ROWT 0
#define EOFF_ROWF 1024
#define EOFF_COLE 2048
#define EOFF_COLS 4096

// gemm1_mma smem: Ah/Al [128][72], Bh/Bl [64][72]
#define G1_AH 0
#define G1_AL TILEB
#define G1_BH (2 * TILEB)
#define G1_BL (2 * TILEB + 64 * PADB * 2)
#define G1_SMEM (2 * TILEB + 2 * 64 * PADB * 2)

__global__ void prep_kernel(const int* __restrict__ w) {
    __shared__ int s;
    __shared__ int cnt[32];
    if (threadIdx.x == 0) s = 0;
    if (threadIdx.x < 32) cnt[threadIdx.x] = 0;
    __syncthreads();
    int local = 0;
    for (int i = threadIdx.x; i < NROWS / 2; i += 256)
        if (w[2 * i + 1] != 0) local = 1;
    if (local) atomicOr(&s, 1);
    __syncthreads();
    const int is32 = s;
    for (int i = threadIdx.x; i < NROWS; i += 256) {
        int l = is32 ? w[i] : w[2 * i];
        g_lab[i] = l;
        if (l >= 0 && l < 32) atomicAdd(&cnt[l], 1);
    }
    __syncthreads();
    if (threadIdx.x < 32) g_cnt[threadIdx.x] = cnt[threadIdx.x];
}

// split roi (fp32) into bf16 hi/lo
__global__ void convert_roi(const float* __restrict__ roi) {
    const int stride = gridDim.x * blockDim.x;
    for (int i = blockIdx.x * blockDim.x + threadIdx.x; i < NROWS * CDIM / 4; i += stride) {
        float4 v = ((const float4*)roi)[i];
        __nv_bfloat16 h0 = __float2bfloat16(v.x), h1 = __float2bfloat16(v.y);
        __nv_bfloat16 h2 = __float2bfloat16(v.z), h3 = __float2bfloat16(v.w);
        __nv_bfloat16 l0 = __float2bfloat16(v.x - __bfloat162float(h0));
        __nv_bfloat16 l1 = __float2bfloat16(v.y - __bfloat162float(h1));
        __nv_bfloat16 l2 = __float2bfloat16(v.z - __bfloat162float(h2));
        __nv_bfloat16 l3 = __float2bfloat16(v.w - __bfloat162float(h3));
        __nv_bfloat16 ph[4] = {h0, h1, h2, h3};
        __nv_bfloat16 pl[4] = {l0, l1, l2, l3};
        *(uint2*)(g_roi_h + i * 4) = *(uint2*)ph;
        *(uint2*)(g_roi_l + i * 4) = *(uint2*)pl;
    }
}

// transpose+split w1 (fp32 [K][N]) into bf16 [head][n][k]
__global__ void convert_w1t(const float* __restrict__ w0, const float* __restrict__ w1) {
    const int stride = gridDim.x * blockDim.x;
    for (int g = blockIdx.x * blockDim.x + threadIdx.x; g < 2 * HDIM * CDIM; g += stride) {
        int head = g >> 18;
        int rem = g & 262143;
        int k = rem >> 8;        // n fastest -> coalesced gmem reads
        int n = rem & 255;
        float v = (head ? w1 : w0)[(size_t)k * HDIM + n];
        __nv_bfloat16 h = __float2bfloat16(v);
        size_t o = (size_t)head * HDIM * CDIM + (size_t)n * CDIM + k;
        g_w1t_h[o] = h;
        g_w1t_l[o] = __float2bfloat16(v - __bfloat162float(h));
    }
}

// layer-1 via split-bf16 mma: grid (64, 4, 2), 256 thr, warp tile 32x32
__global__ void __launch_bounds__(256, 2) gemm1_mma(const float* __restrict__ bias0,
                                                    const float* __restrict__ bias1) {
    extern __shared__ __align__(16) unsigned char smx[];
    const uint32_t sb = s2u(smx);
    const int tid = threadIdx.x, lane = tid & 31, wid = tid >> 5;
    const int row0 = blockIdx.x * 128, col0 = blockIdx.y * 64;
    const int head = blockIdx.z;
    const __nv_bfloat16* Bh = g_w1t_h + (size_t)head * HDIM * CDIM;
    const __nv_bfloat16* Bl = g_w1t_l + (size_t)head * HDIM * CDIM;
    const float* bias = head ? bias1 : bias0;
    float* C = head ? g_h2 : g_h;

    const int wq = wid >> 1, wh = wid & 1;
    const int mr0 = wq * 32, nc0 = wh * 32;
    const int l15 = lane & 15;
    float acc[2][4][4];
#pragma unroll
    for (int m = 0; m < 2; ++m)
#pragma unroll
        for (int n = 0; n < 4; ++n)
#pragma unroll
            for (int c = 0; c < 4; ++c) acc[m][n][c] = 0.f;

    for (int ch = 0; ch < CDIM / 64; ++ch) {
        __syncthreads();
        for (int u = tid; u < 1024; u += 256) {
            int r = u >> 3, c8 = u & 7;
            size_t go = (size_t)(row0 + r) * CDIM + ch * 64 + c8 * 8;
            uint32_t so = (uint32_t)(r * PADB + c8 * 8) * 2;
            *(uint4*)(smx + G1_AH + so) = *(const uint4*)(g_roi_h + go);
            *(uint4*)(smx + G1_AL + so) = *(const uint4*)(g_roi_l + go);
        }
        for (int u = tid; u < 512; u += 256) {
            int r = u >> 3, c8 = u & 7;
            size_t go = (size_t)(col0 + r) * CDIM + ch * 64 + c8 * 8;
            uint32_t so = (uint32_t)(r * PADB + c8 * 8) * 2;
            *(uint4*)(smx + G1_BH + so) = *(const uint4*)(Bh + go);
            *(uint4*)(smx + G1_BL + so) = *(const uint4*)(Bl + go);
        }
        __syncthreads();
#pragma unroll
        for (int ks = 0; ks < 4; ++ks) {
            const int kb = ks * 16;
            uint32_t ah[2][4], al[2][4];
#pragma unroll
            for (int mt = 0; mt < 2; ++mt) {
                int arow = mr0 + mt * 16 + l15;
                int akk = kb + (lane >> 4) * 8;
                uint32_t off = (uint32_t)(arow * PADB + akk) * 2;
                ldm4(ah[mt], sb + G1_AH + off);
                ldm4(al[mt], sb + G1_AL + off);
            }
            uint32_t bh[4][2], bl[4][2];
#pragma unroll
            for (int np = 0; np < 2; ++np) {
                int m = lane >> 3, r = lane & 7;
                int brow = nc0 + np * 16 + (m >> 1) * 8 + r;
                int bkk = kb + (m & 1) * 8;
                uint32_t off = (uint32_t)(brow * PADB + bkk) * 2;
                uint32_t t[4];
                ldm4(t, sb + G1_BH + off);
                bh[2 * np][0] = t[0]; bh[2 * np][1] = t[1];
                bh[2 * np + 1][0] = t[2]; bh[2 * np + 1][1] = t[3];
                ldm4(t, sb + G1_BL + off);
                bl[2 * np][0] = t[0]; bl[2 * np][1] = t[1];
                bl[2 * np + 1][0] = t[2]; bl[2 * np + 1][1] = t[3];
            }
#pragma unroll
            for (int mt = 0; mt < 2; ++mt)
#pragma unroll
                for (int nt = 0; nt < 4; ++nt) {
                    mmabf(acc[mt][nt], ah[mt], bh[nt]);
                    mmabf(acc[mt][nt], ah[mt], bl[nt]);
                    mmabf(acc[mt][nt], al[mt], bh[nt]);
                }
        }
    }
    const int tq = lane >> 2, tr = lane & 3;
#pragma unroll
    for (int mt = 0; mt < 2; ++mt) {
        int r0 = row0 + mr0 + mt * 16 + tq;
        int r1 = r0 + 8;
#pragma unroll
        for (int nt = 0; nt < 4; ++nt) {
            int c = col0 + nc0 + nt * 8 + tr * 2;
            float b0 = bias[c], b1 = bias[c + 1];
            float2 o0, o1;
            o0.x = fmaxf(acc[mt][nt][0] + b0, 0.f);
            o0.y = fmaxf(acc[mt][nt][1] + b1, 0.f);
            o1.x = fmaxf(acc[mt][nt][2] + b0, 0.f);
            o1.y = fmaxf(acc[mt][nt][3] + b1, 0.f);
            *(float2*)(C + (size_t)r0 * HDIM + c) = o0;
            *(float2*)(C + (size_t)r1 * HDIM + c) = o1;
        }
    }
}

__global__ void __launch_bounds__(256) gemm2_fused(const float* __restrict__ Bf,
                                                   const float* __restrict__ bf,
                                                   const float* __restrict__ Bc,
                                                   const float* __restrict__ bc) {
    __shared__ float As[2][16][132];
    __shared__ float Bs[2][16][132];
    const int tid = threadIdx.x;
    const int ty = tid >> 4, tx = tid & 15;
    const int mA = tid >> 2, kA = (tid & 3) << 2;
    const int row0 = blockIdx.x * 128;
    const int TI = HDIM >> 4;

    if (blockIdx.y == 0) {
        const int kB = tid >> 4, nB = (tid & 15) << 2;
        u64 acc2[4][4];
#pragma unroll
        for (int i = 0; i < 4; ++i)
#pragma unroll
            for (int j = 0; j < 4; ++j) acc2[i][j] = 0ull;
        const float* pA0 = g_h + (size_t)(row0 + mA) * HDIM + kA;
        const float* pA1 = g_h + (size_t)(row0 + mA + 64) * HDIM + kA;
        const float* pB = Bf + (size_t)kB * DFG + nB;
        float4 ra0 = *(const float4*)pA0;
        float4 ra1 = *(const float4*)pA1;
        float4 rb = *(const float4*)pB;
        As[0][kA + 0][mA] = ra0.x; As[0][kA + 1][mA] = ra0.y;
        As[0][kA + 2][mA] = ra0.z; As[0][kA + 3][mA] = ra0.w;
        As[0][kA + 0][mA + 64] = ra1.x; As[0][kA + 1][mA + 64] = ra1.y;
        As[0][kA + 2][mA + 64] = ra1.z; As[0][kA + 3][mA + 64] = ra1.w;
        *(float4*)&Bs[0][kB][nB] = rb;
        __syncthreads();
        for (int t = 0; t < TI; ++t) {
            const int cur = t & 1;
            if (t + 1 < TI) {
                const int k0 = (t + 1) << 4;
                ra0 = *(const float4*)(pA0 + k0);
                ra1 = *(const float4*)(pA1 + k0);
                rb = *(const float4*)(pB + (size_t)k0 * DFG);
            }
#pragma unroll
            for (int kk = 0; kk < 16; ++kk) {
                const float* ar = &As[cur][kk][ty * 8];
                ulonglong2 a01 = *(const ulonglong2*)ar;
                ulonglong2 a23 = *(const ulonglong2*)(ar + 4);
                u64 pa[4] = {a01.x, a01.y, a23.x, a23.y};
                float4 b = *(const float4*)&Bs[cur][kk][tx * 4];
                u64 pb[4] = {bcast2(b.x), bcast2(b.y), bcast2(b.z), bcast2(b.w)};
#pragma unroll
                for (int i = 0; i < 4; ++i)
#pragma unroll
                    for (int j = 0; j < 4; ++j) fma2(acc2[i][j], pa[i], pb[j]);
            }
            if (t + 1 < TI) {
                const int nxt = cur ^ 1;
                As[nxt][kA + 0][mA] = ra0.x; As[nxt][kA + 1][mA] = ra0.y;
                As[nxt][kA + 2][mA] = ra0.z; As[nxt][kA + 3][mA] = ra0.w;
                As[nxt][kA + 0][mA + 64] = ra1.x; As[nxt][kA + 1][mA + 64] = ra1.y;
                As[nxt][kA + 2][mA + 64] = ra1.z; As[nxt][kA + 3][mA + 64] = ra1.w;
                *(float4*)&Bs[nxt][kB][nB] = rb;
            }
            __syncthreads();
        }
        float4 bb = *(const float4*)(bf + tx * 4);
        float bv[4] = {bb.x, bb.y, bb.z, bb.w};
        float v[8][4];
#pragma unroll
        for (int i2 = 0; i2 < 4; ++i2)
#pragma unroll
            for (int j = 0; j < 4; ++j) {
                float2 p = unpack2(acc2[i2][j]);
                v[2 * i2][j] = p.x + bv[j];
                v[2 * i2 + 1][j] = p.y + bv[j];
            }
#pragma unroll
        for (int r = 0; r < 8; ++r) {
            float s = v[r][0] * v[r][0] + v[r][1] * v[r][1] +
                      v[r][2] * v[r][2] + v[r][3] * v[r][3];
#pragma unroll
            for (int off = 8; off > 0; off >>= 1) s += __shfl_xor_sync(0xffffffffu, s, off, 16);
            float inv = 1.f / fmaxf(sqrtf(s), EPSF);
            float4 o;
            o.x = v[r][0] * inv; o.y = v[r][1] * inv;
            o.z = v[r][2] * inv; o.w = v[r][3] * inv;
            *(float4*)(g_zfg + (size_t)(row0 + ty * 8 + r) * DFG + tx * 4) = o;
        }
    } else {
        const int kB = tid >> 4, nB = (tid & 15) << 3;
        u64 acc2[4][8];
#pragma unroll
        for (int i = 0; i < 4; ++i)
#pragma unroll
            for (int j = 0; j < 8; ++j) acc2[i][j] = 0ull;
        const float* pA0 = g_h2 + (size_t)(row0 + mA) * HDIM + kA;
        const float* pA1 = g_h2 + (size_t)(row0 + mA + 64) * HDIM + kA;
        const float* pB = Bc + (size_t)kB * DCLS + nB;
        float4 ra0 = *(const float4*)pA0;
        float4 ra1 = *(const float4*)pA1;
        float4 rb0 = *(const float4*)pB;
        float4 rb1 = *(const float4*)(pB + 4);
        As[0][kA + 0][mA] = ra0.x; As[0][kA + 1][mA] = ra0.y;
        As[0][kA + 2][mA] = ra0.z; As[0][kA + 3][mA] = ra0.w;
        As[0][kA + 0][mA + 64] = ra1.x; As[0][kA + 1][mA + 64] = ra1.y;
        As[0][kA + 2][mA + 64] = ra1.z; As[0][kA + 3][mA + 64] = ra1.w;
        *(float4*)&Bs[0][kB][nB] = rb0;
        *(float4*)&Bs[0][kB][nB + 4] = rb1;
        __syncthreads();
        for (int t = 0; t < TI; ++t) {
            const int cur = t & 1;
            if (t + 1 < TI) {
                const int k0 = (t + 1) << 4;
                ra0 = *(const float4*)(pA0 + k0);
                ra1 = *(const float4*)(pA1 + k0);
                rb0 = *(const float4*)(pB + (size_t)k0 * DCLS);
                rb1 = *(const float4*)(pB + (size_t)k0 * DCLS + 4);
            }
#pragma unroll
            for (int kk = 0; kk < 16; ++kk) {
                const float* ar = &As[cur][kk][ty * 8];
                ulonglong2 a01 = *(const ulonglong2*)ar;
                ulonglong2 a23 = *(const ulonglong2*)(ar + 4);
                u64 pa[4] = {a01.x, a01.y, a23.x, a23.y};
                float4 b0 = *(const float4*)&Bs[cur][kk][tx * 4];
                float4 b1 = *(const float4*)&Bs[cur][kk][64 + tx * 4];
                u64 pb[8] = {bcast2(b0.x), bcast2(b0.y), bcast2(b0.z), bcast2(b0.w),
                             bcast2(b1.x), bcast2(b1.y), bcast2(b1.z), bcast2(b1.w)};
#pragma unroll
                for (int i = 0; i < 4; ++i)
#pragma unroll
                    for (int j = 0; j < 8; ++j) fma2(acc2[i][j], pa[i], pb[j]);
            }
            if (t + 1 < TI) {
                const int nxt = cur ^ 1;
                As[nxt][kA + 0][mA] = ra0.x; As[nxt][kA + 1][mA] = ra0.y;
                As[nxt][kA + 2][mA] = ra0.z; As[nxt][kA + 3][mA] = ra0.w;
                As[nxt][kA + 0][mA + 64] = ra1.x; As[nxt][kA + 1][mA + 64] = ra1.y;
                As[nxt][kA + 2][mA + 64] = ra1.z; As[nxt][kA + 3][mA + 64] = ra1.w;
                *(float4*)&Bs[nxt][kB][nB] = rb0;
                *(float4*)&Bs[nxt][kB][nB + 4] = rb1;
            }
            __syncthreads();
        }
        float4 bb0 = *(const float4*)(bc + tx * 4);
        float4 bb1 = *(const float4*)(bc + 64 + tx * 4);
        float bv[8] = {bb0.x, bb0.y, bb0.z, bb0.w, bb1.x, bb1.y, bb1.z, bb1.w};
        float v[8][8];
#pragma unroll
        for (int i2 = 0; i2 < 4; ++i2)
#pragma unroll
            for (int j = 0; j < 8; ++j) {
                float2 p = unpack2(acc2[i2][j]);
                v[2 * i2][j] = p.x + bv[j];
                v[2 * i2 + 1][j] = p.y + bv[j];
            }
#pragma unroll
        for (int r = 0; r < 8; ++r) {
            float s = 0.f;
#pragma unroll
            for (int j = 0; j < 8; ++j) s += v[r][j] * v[r][j];
#pragma unroll
            for (int off = 8; off > 0; off >>= 1) s += __shfl_xor_sync(0xffffffffu, s, off, 16);
            float inv = 1.f / fmaxf(sqrtf(s), EPSF);
            float4 o0, o1;
            o0.x = v[r][0] * inv; o0.y = v[r][1] * inv;
            o0.z = v[r][2] * inv; o0.w = v[r][3] * inv;
            o1.x = v[r][4] * inv; o1.y = v[r][5] * inv;
            o1.z = v[r][6] * inv; o1.w = v[r][7] * inv;
            *(float4*)(g_zcls + (size_t)(row0 + ty * 8 + r) * DCLS + tx * 4) = o0;
            *(float4*)(g_zcls + (size_t)(row0 + ty * 8 + r) * DCLS + 64 + tx * 4) = o1;
        }
    }
}

__global__ void convert_kernel() {
    const int stride = gridDim.x * blockDim.x;
    int g = blockIdx.x * blockDim.x + threadIdx.x;
    for (int i = g; i < NROWS * DFG; i += stride) {
        float z = g_zfg[i];
        __nv_bfloat16 h = __float2bfloat16(z);
        g_zfg_h[i] = h;
        g_zfg_l[i] = __float2bfloat16(z - __bfloat162float(h));
    }
    for (int i = g; i < NROWS * DCLS; i += stride) {
        float z = g_zcls[i];
        __nv_bfloat16 h = __float2bfloat16(z);
        g_zcls_h[i] = h;
        g_zcls_l[i] = __float2bfloat16(z - __bfloat162float(h));
    }
}

__device__ __forceinline__ void decode_pair(int t, int& I, int& J) {
    int i = (int)((129.0f - sqrtf(16641.0f - 8.0f * (float)t)) * 0.5f);
    if (i < 0) i = 0;
    if (i > NT - 1) i = NT - 1;
    while (i * (129 - i) / 2 > t) --i;
    while ((i + 1) * (128 - i) / 2 <= t) ++i;
    I = i;
    J = i + (t - i * (129 - i) / 2);
}

__global__ void __launch_bounds__(256, 2) sim_mma() {
    extern __shared__ __align__(16) unsigned char smx[];
    const uint32_t sb = s2u(smx);
    const int tid = threadIdx.x;
    const int wid = tid >> 5, lane = tid & 31;
    const bool cls = blockIdx.x < NPAIRS;
    const int pidx = cls ? blockIdx.x : blockIdx.x - NPAIRS;
    int I, J;
    decode_pair(pidx, I, J);
    const int row0 = I * 128, col0 = J * 128;
    const bool diag = (I == J);
    const int Dtot = cls ? DCLS : DFG;
    const int nch = cls ? 2 : 1;
    const __nv_bfloat16* zh = cls ? g_zcls_h : g_zfg_h;
    const __nv_bfloat16* zl = cls ? g_zcls_l : g_zfg_l;

    int* labI = (int*)(smx + OFF_LAB);
    int* labJ = labI + 128;
    float* fgI = (float*)(labJ + 128);
    float* fgJ = fgI + 128;
    if (tid < 128) {
        int li = g_lab[row0 + tid], lj = g_lab[col0 + tid];
        labI[tid] = li; labJ[tid] = lj;
        fgI[tid] = (li > 0) ? 1.f : 0.f;
        fgJ[tid] = (lj > 0) ? 1.f : 0.f;
    }

    const int wq = wid >> 1, wh = wid & 1;
    const int mr0 = wq * 32, nc0 = wh * 64;
    float acc[2][8][4];
#pragma unroll
    for (int m = 0; m < 2; ++m)
#pragma unroll
        for (int n = 0; n < 8; ++n)
#pragma unroll
            for (int c = 0; c < 4; ++c) acc[m][n][c] = 0.f;

    const int l15 = lane & 15;
    for (int ch = 0; ch < nch; ++ch) {
        __syncthreads();
#pragma unroll
        for (int m = 0; m < 4; ++m) {
            const __nv_bfloat16* src =
                ((m & 1) ? zl : zh) + (size_t)((m < 2) ? row0 : col0) * Dtot + ch * 64;
            __nv_bfloat16* dst = (__nv_bfloat16*)(smx + ((m < 2) ? (m ? OFF_AL : OFF_AH)
                                                                 : (m == 2 ? OFF_BH : OFF_BL)));
            for (int u = tid; u < 1024; u += 256) {
                int r = u >> 3, c8 = u & 7;
                uint4 v = *(const uint4*)(src + (size_t)r * Dtot + c8 * 8);
                *(uint4*)(dst + r * PADB + c8 * 8) = v;
            }
        }
        __syncthreads();
#pragma unroll
        for (int ks = 0; ks < 4; ++ks) {
            const int kb = ks * 16;
            uint32_t ah[2][4], al[2][4];
#pragma unroll
            for (int mt = 0; mt < 2; ++mt) {
                int arow = mr0 + mt * 16 + l15;
                int akk = kb + (lane >> 4) * 8;
                uint32_t off = (uint32_t)(arow * PADB + akk) * 2;
                ldm4(ah[mt], sb + OFF_AH + off);
                ldm4(al[mt], sb + OFF_AL + off);
            }
#pragma unroll
            for (int nt = 0; nt < 8; ++nt) {
                int brow = nc0 + nt * 8 + (l15 & 7);
                int bkk = kb + ((l15 >> 3) & 1) * 8;
                uint32_t off = (uint32_t)(brow * PADB + bkk) * 2;
                uint32_t bh[2], bl[2];
                ldm2(bh, sb + OFF_BH + off);
                ldm2(bl, sb + OFF_BL + off);
#pragma unroll
                for (int mt = 0; mt < 2; ++mt) {
                    mmabf(acc[mt][nt], ah[mt], bh);
                    mmabf(acc[mt][nt], ah[mt], bl);
                    mmabf(acc[mt][nt], al[mt], bh);
                }
            }
        }
    }
    __syncthreads();

    float* rowT = (float*)(smx + EOFF_ROWT);
    float* rowF = (float*)(smx + EOFF_ROWF);
    float* colE = (float*)(smx + EOFF_COLE);
    float* colS = (float*)(smx + EOFF_COLS);
    const int tq = lane >> 2, tr = lane & 3;

    float colPE[8][2], colPS[8][2];
#pragma unroll
    for (int n = 0; n < 8; ++n) { colPE[n][0] = colPE[n][1] = 0.f; colPS[n][0] = colPS[n][1] = 0.f; }

#pragma unroll
    for (int mt = 0; mt < 2; ++mt) {
        const int r0 = mr0 + mt * 16 + tq, r1 = r0 + 8;
        const int lab0 = labI[r0], lab1 = labI[r1];
        const float fg0 = fgI[r0], fg1 = fgI[r1];
        float rA0 = 0.f, rB0 = 0.f, rA1 = 0.f, rB1 = 0.f;
#pragma unroll
        for (int n = 0; n < 8; ++n) {
            const int c0 = nc0 + n * 8 + tr * 2, c1 = c0 + 1;
            float s00 = acc[mt][n][0] * TAU_INV, s01 = acc[mt][n][1] * TAU_INV;
            float s10 = acc[mt][n][2] * TAU_INV, s11 = acc[mt][n][3] * TAU_INV;
            float e00 = __expf(s00), e01 = __expf(s01);
            float e10 = __expf(s10), e11 = __expf(s11);
            rA0 += e00 + e01; rA1 += e10 + e11;
            colPE[n][0] += e00 + e10; colPE[n][1] += e01 + e11;
            if (cls) {
                int lc0 = labJ[c0], lc1 = labJ[c1];
                if (lc0 > 0) {
                    if (lc0 == lab0) rB0 += s00;
                    if (lc0 == lab1) rB1 += s10;
                    float t = ((lc0 == lab0) ? s00 : 0.f) + ((lc0 == lab1) ? s10 : 0.f);
                    colPS[n][0] += t;
                }
                if (lc1 > 0) {
                    if (lc1 == lab0) rB0 += s01;
                    if (lc1 == lab1) rB1 += s11;
                    float t = ((lc1 == lab0) ? s01 : 0.f) + ((lc1 == lab1) ? s11 : 0.f);
                    colPS[n][1] += t;
                }
            } else {
                float fj0 = fgJ[c0], fj1 = fgJ[c1];
                rB0 += e00 * fj0 + e01 * fj1;
                rB1 += e10 * fj0 + e11 * fj1;
                colPS[n][0] += e00 * fg0 + e10 * fg1;
                colPS[n][1] += e01 * fg0 + e11 * fg1;
            }
        }
        rA0 += __shfl_xor_sync(0xffffffffu, rA0, 1);
        rA0 += __shfl_xor_sync(0xffffffffu, rA0, 2);
        rB0 += __shfl_xor_sync(0xffffffffu, rB0, 1);
        rB0 += __shfl_xor_sync(0xffffffffu, rB0, 2);
        rA1 += __shfl_xor_sync(0xffffffffu, rA1, 1);
        rA1 += __shfl_xor_sync(0xffffffffu, rA1, 2);
        rB1 += __shfl_xor_sync(0xffffffffu, rB1, 1);
        rB1 += __shfl_xor_sync(0xffffffffu, rB1, 2);
        if (tr == 0) {
            rowT[wh * 128 + r0] = rA0; rowF[wh * 128 + r0] = rB0;
            rowT[wh * 128 + r1] = rA1; rowF[wh * 128 + r1] = rB1;
        }
    }
#pragma unroll
    for (int n = 0; n < 8; ++n) {
#pragma unroll
        for (int h = 0; h < 2; ++h) {
            float e = colPE[n][h], s = colPS[n][h];
            e += __shfl_xor_sync(0xffffffffu, e, 4);
            e += __shfl_xor_sync(0xffffffffu, e, 8);
            e += __shfl_xor_sync(0xffffffffu, e, 16);
            s += __shfl_xor_sync(0xffffffffu, s, 4);
            s += __shfl_xor_sync(0xffffffffu, s, 8);
            s += __shfl_xor_sync(0xffffffffu, s, 16);
            if (tq == 0) {
                int c = nc0 + n * 8 + tr * 2 + h;
                colE[wq * 128 + c] = e;
                colS[wq * 128 + c] = s;
            }
        }
    }
    __syncthreads();
    if (tid < 128) {
        float rA = rowT[tid] + rowT[128 + tid];
        float rB = rowF[tid] + rowF[128 + tid];
        if (cls) {
            g_E[(size_t)J * NROWS + row0 + tid] = rA;
            g_SP[(size_t)J * NROWS + row0 + tid] = rB;
        } else {
            g_T[(size_t)J * NROWS + row0 + tid] = rA;
            g_F[(size_t)J * NROWS + row0 + tid] = rB;
        }
        if (!diag) {
            float cE = colE[tid] + colE[128 + tid] + colE[256 + tid] + colE[384 + tid];
            float cS = colS[tid] + colS[128 + tid] + colS[256 + tid] + colS[384 + tid];
            if (cls) {
                g_E[(size_t)I * NROWS + col0 + tid] = cE;
                g_SP[(size_t)I * NROWS + col0 + tid] = cS;
            } else {
                g_T[(size_t)I * NROWS + col0 + tid] = cE;
                g_F[(size_t)I * NROWS + col0 + tid] = cS;
            }
        }
    }
}

__global__ void __launch_bounds__(256) rowfinal_kernel(const float* __restrict__ ious) {
    const int wid = threadIdx.x >> 5, lane = threadIdx.x & 31;
    const int row = blockIdx.x * 8 + wid;

    float T = 0.f, F = 0.f, E = 0.f, SP = 0.f;
#pragma unroll
    for (int s = lane; s < NT; s += 32) {
        T += g_T[(size_t)s * NROWS + row];
        F += g_F[(size_t)s * NROWS + row];
        E += g_E[(size_t)s * NROWS + row];
        SP += g_SP[(size_t)s * NROWS + row];
    }
#pragma unroll
    for (int off = 16; off > 0; off >>= 1) {
        T += __shfl_xor_sync(0xffffffffu, T, off);
        F += __shfl_xor_sync(0xffffffffu, F, off);
        E += __shfl_xor_sync(0xffffffffu, E, off);
        SP += __shfl_xor_sync(0xffffffffu, SP, off);
    }

    __shared__ double red[8][4];
    if (lane == 0) {
        int l = g_lab[row];
        bool fg = (l > 0);
        float iou = ious[row];
        float iouw = (iou > 0.5f) ? iou : 0.f;

        float hh = 0.f, hl2 = 0.f;
        {
            const __nv_bfloat16* zh = g_zfg_h + (size_t)row * DFG;
            const __nv_bfloat16* zl = g_zfg_l + (size_t)row * DFG;
            for (int d = 0; d < DFG; ++d) {
                float h = __bfloat162float(zh[d]), lo = __bfloat162float(zl[d]);
                hh += h * h;
                hl2 += 2.f * h * lo;
            }
        }
        float eii = __expf((hh + hl2) * TAU_INV);
        float Tex = T - eii;
        float Fex = F - (fg ? eii : 0.f);
        int nfg = NROWS - g_cnt[0];
        int n_pos = nfg - (fg ? 1 : 0);
        bool valid = fg && (n_pos > 0);
        float lossi = -logf((Fex + EPSF) / (Tex + 2.0f * EPSF));
        float w = valid ? iouw : 0.f;

        float chh = 0.f, chl = 0.f;
        {
            const __nv_bfloat16* zh = g_zcls_h + (size_t)row * DCLS;
            const __nv_bfloat16* zl = g_zcls_l + (size_t)row * DCLS;
            for (int d = 0; d < DCLS; ++d) {
                float h = __bfloat162float(zh[d]), lo = __bfloat162float(zl[d]);
                chh += h * h;
                chl += 2.f * h * lo;
            }
        }
        float sii_c = (chh + chl) * TAU_INV;
        float Eex = E - __expf(sii_c);
        float SPex = SP - ((l > 0) ? sii_c : 0.f);
        float npc = (l > 0) ? (float)g_cnt[l] : 0.f;
        float dg = (l > 0) ? 1.f : 0.f;
        float L = logf(Eex);
        float slp = dg * NEGV + SPex - (npc - dg) * L;
        bool validc = fg && (npc > 0.f) && isfinite(L);
        float Lzi = validc ? (-slp / (npc + EPSF)) : 0.f;
        float wcv = validc ? iouw : 0.f;

        red[wid][0] = (double)w * (double)lossi;
        red[wid][1] = (double)w;
        red[wid][2] = (double)wcv * (double)Lzi;
        red[wid][3] = (double)wcv;
    }
    __syncthreads();
    if (threadIdx.x == 0) {
        double s0 = 0, s1 = 0, s2 = 0, s3 = 0;
#pragma unroll
        for (int i = 0; i < 8; ++i) {
            s0 += red[i][0]; s1 += red[i][1];
            s2 += red[i][2]; s3 += red[i][3];
        }
        g_bred[blockIdx.x * 4 + 0] = s0;
        g_bred[blockIdx.x * 4 + 1] = s1;
        g_bred[blockIdx.x * 4 + 2] = s2;
        g_bred[blockIdx.x * 4 + 3] = s3;
    }
}

__global__ void final_kernel(float* __restrict__ out) {
    __shared__ double sh[256][4];
    double a[4] = {0, 0, 0, 0};
    for (int b = threadIdx.x; b < NROWS / 8; b += 256) {
#pragma unroll
        for (int c = 0; c < 4; ++c) a[c] += g_bred[b * 4 + c];
    }
#pragma unroll
    for (int c = 0; c < 4; ++c) sh[threadIdx.x][c] = a[c];
    __syncthreads();
    for (int s = 128; s > 0; s >>= 1) {
        if (threadIdx.x < s) {
#pragma unroll
            for (int c = 0; c < 4; ++c) sh[threadIdx.x][c] += sh[threadIdx.x + s][c];
        }
        __syncthreads();
    }
    if (threadIdx.x == 0) {
        out[0] = (float)(sh[0][0] / (sh[0][1] + (double)EPSF));
        out[1] = (float)(sh[0][2] / (sh[0][3] + (double)EPSF));
    }
}

extern "C" void kernel_launch(void* const* d_in, const int* in_sizes, int n_in,
                              void* d_out, int out_size) {
    const float* roi   = (const float*)d_in[0];
    const int*   labw  = (const int*)d_in[1];
    const float* ious  = (const float*)d_in[2];
    const float* fg_w1 = (const float*)d_in[3];
    const float* fg_b1 = (const float*)d_in[4];
    const float* fg_w2 = (const float*)d_in[5];
    const float* fg_b2 = (const float*)d_in[6];
    const float* cl_w1 = (const float*)d_in[7];
    const float* cl_b1 = (const float*)d_in[8];
    const float* cl_w2 = (const float*)d_in[9];
    const float* cl_b2 = (const float*)d_in[10];
    float* out = (float*)d_out;

    static bool init = false;
    if (!init) {
        cudaFuncSetAttribute(sim_mma, cudaFuncAttributeMaxDynamicSharedMemorySize, SMEM_SIM);
        cudaFuncSetAttribute(gemm1_mma, cudaFuncAttributeMaxDynamicSharedMemorySize, G1_SMEM);
        init = true;
    }

    prep_kernel<<<1, 256>>>(labw);
    convert_roi<<<1024, 256>>>(roi);
    convert_w1t<<<512, 256>>>(fg_w1, cl_w1);
    gemm1_mma<<<dim3(NROWS / 128, HDIM / 64, 2), 256, G1_SMEM>>>(fg_b1, cl_b1);
    gemm2_fused<<<dim3(NROWS / 128, 2), 256>>>(fg_w2, fg_b2, cl_w2, cl_b2);
    convert_kernel<<<512, 256>>>();

    sim_mma<<<2 * NPAIRS, 256, SMEM_SIM>>>();

    rowfinal_kernel<<<NROWS / 8, 256>>>(ious);
    final_kernel<<<1, 256>>>(out);
}